// round 3
// baseline (speedup 1.0000x reference)
#include <cuda_runtime.h>
#include <cuda_bf16.h>

#define B_  2
#define S_  2048
#define D_  1024
#define H_  8
#define E_  128
#define KW_ 16
#define M_  (B_ * S_)        // 4096 rows

// ---------------------------------------------------------------------------
// Scratch (allocation-free: __device__ globals)
// q/k/v: [B, H, S, E]    attn: [B, S, H, E]
// ---------------------------------------------------------------------------
__device__ float g_q[4194304];
__device__ float g_k[4194304];
__device__ float g_v[4194304];
__device__ float g_attn[4194304];

// ---------------------------------------------------------------------------
// 128x128 tile SGEMM core, K = 1024, BK = 8, 256 threads, 8x8 per thread.
// A: row-major, lda given (element (m_local, k) = A[m_local*lda + k])
// B: row-major, ldb given (element (k, n_local) = Bb[k*ldb + n_local])
// ---------------------------------------------------------------------------
__device__ __forceinline__ void gemm_core_128x128(
    const float* __restrict__ A, int lda,
    const float* __restrict__ Bb, int ldb,
    float acc[8][8])
{
    __shared__ float As[8][128];
    __shared__ float Bs[8][128];

    const int tid  = threadIdx.x;
    const int arow = tid >> 1;          // 0..127
    const int acol = (tid & 1) << 2;    // 0 or 4
    const int brow = tid >> 5;          // 0..7
    const int bcol = (tid & 31) << 2;   // 0..124 step 4
    const int ty   = tid >> 4;          // 0..15
    const int tx   = tid & 15;          // 0..15

    for (int kt = 0; kt < D_; kt += 8) {
        float4 a4 = *(const float4*)(A + (size_t)arow * lda + kt + acol);
        float4 b4 = *(const float4*)(Bb + (size_t)(kt + brow) * ldb + bcol);
        __syncthreads();
        As[acol + 0][arow] = a4.x;
        As[acol + 1][arow] = a4.y;
        As[acol + 2][arow] = a4.z;
        As[acol + 3][arow] = a4.w;
        *(float4*)&Bs[brow][bcol] = b4;
        __syncthreads();
#pragma unroll
        for (int kk = 0; kk < 8; kk++) {
            float ar[8], br[8];
            *(float4*)&ar[0] = *(const float4*)&As[kk][ty * 8];
            *(float4*)&ar[4] = *(const float4*)&As[kk][ty * 8 + 4];
            *(float4*)&br[0] = *(const float4*)&Bs[kk][tx * 8];
            *(float4*)&br[4] = *(const float4*)&Bs[kk][tx * 8 + 4];
#pragma unroll
            for (int i = 0; i < 8; i++)
#pragma unroll
                for (int j = 0; j < 8; j++)
                    acc[i][j] = fmaf(ar[i], br[j], acc[i][j]);
        }
    }
}

// ---------------------------------------------------------------------------
// Q/K/V projection: q[b,h,s,e] = sum_d x[b,s,d] * W[h,d,e] + bias[h,e]
// grid: (M_/128, H, 3)  z selects {q, k, v}
// ---------------------------------------------------------------------------
__global__ __launch_bounds__(256, 2) void proj_kernel(
    const float* __restrict__ x,
    const float* __restrict__ Wq, const float* __restrict__ bq,
    const float* __restrict__ Wk, const float* __restrict__ bk,
    const float* __restrict__ Wv, const float* __restrict__ bv)
{
    const int sel = blockIdx.z;
    const float* W  = (sel == 0) ? Wq : (sel == 1 ? Wk : Wv);
    const float* bi = (sel == 0) ? bq : (sel == 1 ? bk : bv);
    float* out      = (sel == 0) ? g_q : (sel == 1 ? g_k : g_v);

    const int h  = blockIdx.y;
    const int m0 = blockIdx.x * 128;

    float acc[8][8] = {};
    gemm_core_128x128(x + (size_t)m0 * D_, D_,
                      W + (size_t)h * D_ * E_, E_, acc);

    const int ty = threadIdx.x >> 4;
    const int tx = threadIdx.x & 15;
    const int e0 = tx * 8;
    float bias[8];
#pragma unroll
    for (int j = 0; j < 8; j++) bias[j] = bi[h * E_ + e0 + j];

#pragma unroll
    for (int i = 0; i < 8; i++) {
        const int m = m0 + ty * 8 + i;
        const int bb = m >> 11;          // / S_
        const int s  = m & (S_ - 1);
        float* crow = out + (((size_t)bb * H_ + h) * S_ + s) * E_ + e0;
        float4 c0, c1;
        c0.x = acc[i][0] + bias[0]; c0.y = acc[i][1] + bias[1];
        c0.z = acc[i][2] + bias[2]; c0.w = acc[i][3] + bias[3];
        c1.x = acc[i][4] + bias[4]; c1.y = acc[i][5] + bias[5];
        c1.z = acc[i][6] + bias[6]; c1.w = acc[i][7] + bias[7];
        *(float4*)(crow)     = c0;
        *(float4*)(crow + 4) = c1;
    }
}

// ---------------------------------------------------------------------------
// Windowed attention: one warp per (b, h, s) query.
// logits_j = q . kw_j ; softmax over KW; attn = (sum_j p_j * vw_j) / sqrt(E)
// Invalid (out-of-range) window positions use the bias rows bk[h], bv[h].
// attn written as [B, S, H, E].
// ---------------------------------------------------------------------------
__global__ __launch_bounds__(256) void attn_kernel(
    const float* __restrict__ bk,
    const float* __restrict__ bv,
    const int*   __restrict__ dilations)
{
    const int warp = (blockIdx.x * blockDim.x + threadIdx.x) >> 5;
    const int lane = threadIdx.x & 31;
    // warp = (b*H + h)*S + s
    const int s = warp & (S_ - 1);
    const int h = (warp >> 11) & (H_ - 1);
    const int b = warp >> 14;

    const int d = dilations[h];
    const int center = (d * (KW_ - 1)) >> 1;

    const size_t head_base = ((size_t)b * H_ + h) * S_ * E_;
    const float4 q4 = ((const float4*)(g_q + head_base + (size_t)s * E_))[lane];
    const float4* kbase = (const float4*)(g_k + head_base);
    const float4* vbase = (const float4*)(g_v + head_base);
    const float4 bk4 = ((const float4*)(bk + h * E_))[lane];
    const float4 bv4 = ((const float4*)(bv + h * E_))[lane];

    float logits[KW_];
    float4 vreg[KW_];

#pragma unroll
    for (int j = 0; j < KW_; j++) {
        const int pos = s + d * j - center;
        const bool ok = (pos >= 0) && (pos < S_);
        float4 k4;
        if (ok) {
            k4      = kbase[(size_t)pos * 32 + lane];
            vreg[j] = vbase[(size_t)pos * 32 + lane];
        } else {
            k4      = bk4;
            vreg[j] = bv4;
        }
        float p = q4.x * k4.x + q4.y * k4.y + q4.z * k4.z + q4.w * k4.w;
#pragma unroll
        for (int o = 16; o > 0; o >>= 1)
            p += __shfl_xor_sync(0xffffffffu, p, o);
        logits[j] = p;
    }

    // softmax over KW
    float mx = logits[0];
#pragma unroll
    for (int j = 1; j < KW_; j++) mx = fmaxf(mx, logits[j]);
    float ssum = 0.f;
#pragma unroll
    for (int j = 0; j < KW_; j++) {
        logits[j] = __expf(logits[j] - mx);
        ssum += logits[j];
    }
    const float inv = 0.08838834764831845f / ssum;  // (1/sum) * (1/sqrt(E))

    float4 acc = make_float4(0.f, 0.f, 0.f, 0.f);
#pragma unroll
    for (int j = 0; j < KW_; j++) {
        const float w = logits[j] * inv;
        acc.x += w * vreg[j].x;
        acc.y += w * vreg[j].y;
        acc.z += w * vreg[j].z;
        acc.w += w * vreg[j].w;
    }

    // attn[b, s, h, e]
    float4* arow = (float4*)(g_attn + (((size_t)b * S_ + s) * H_ + h) * E_);
    arow[lane] = acc;
}

// ---------------------------------------------------------------------------
// Output projection: out[b,s,d] = sum_{h,e} attn[b,s,h,e] * Wo[h,e,d] + bo[d]
// attn is [4096, 1024] row-major; Wo flattened is [1024, 1024] row-major.
// grid: (M_/128, D_/128)
// ---------------------------------------------------------------------------
__global__ __launch_bounds__(256, 2) void outproj_kernel(
    const float* __restrict__ Wo,
    const float* __restrict__ bo,
    float* __restrict__ out)
{
    const int m0 = blockIdx.x * 128;
    const int n0 = blockIdx.y * 128;

    float acc[8][8] = {};
    gemm_core_128x128(g_attn + (size_t)m0 * (H_ * E_), H_ * E_,
                      Wo + n0, D_, acc);

    const int ty = threadIdx.x >> 4;
    const int tx = threadIdx.x & 15;
    float bias[8];
#pragma unroll
    for (int j = 0; j < 8; j++) bias[j] = bo[n0 + tx * 8 + j];

#pragma unroll
    for (int i = 0; i < 8; i++) {
        const int m = m0 + ty * 8 + i;
        float* crow = out + (size_t)m * D_ + n0 + tx * 8;
        float4 c0, c1;
        c0.x = acc[i][0] + bias[0]; c0.y = acc[i][1] + bias[1];
        c0.z = acc[i][2] + bias[2]; c0.w = acc[i][3] + bias[3];
        c1.x = acc[i][4] + bias[4]; c1.y = acc[i][5] + bias[5];
        c1.z = acc[i][6] + bias[6]; c1.w = acc[i][7] + bias[7];
        *(float4*)(crow)     = c0;
        *(float4*)(crow + 4) = c1;
    }
}

// ---------------------------------------------------------------------------
// Launch
// ---------------------------------------------------------------------------
extern "C" void kernel_launch(void* const* d_in, const int* in_sizes, int n_in,
                              void* d_out, int out_size)
{
    const float* x  = (const float*)d_in[0];
    const float* Wq = (const float*)d_in[1];
    const float* bq = (const float*)d_in[2];
    const float* Wk = (const float*)d_in[3];
    const float* bk = (const float*)d_in[4];
    const float* Wv = (const float*)d_in[5];
    const float* bv = (const float*)d_in[6];
    const float* Wo = (const float*)d_in[7];
    const float* bo = (const float*)d_in[8];
    const int*   dl = (const int*)d_in[9];
    float* out = (float*)d_out;

    dim3 gp(M_ / 128, H_, 3);
    proj_kernel<<<gp, 256>>>(x, Wq, bq, Wk, bk, Wv, bv);

    attn_kernel<<<(B_ * H_ * S_) / 8, 256>>>(bk, bv, dl);

    dim3 go(M_ / 128, D_ / 128);
    outproj_kernel<<<go, 256>>>(Wo, bo, out);
}

// round 10
// speedup vs baseline: 2.0349x; 2.0349x over previous
#include <cuda_runtime.h>
#include <cuda_bf16.h>
#include <cstdint>

#define B_  2
#define S_  2048
#define D_  1024
#define H_  8
#define E_  128
#define KW_ 16
#define M_  (B_ * S_)        // 4096 rows

// ---------------------------------------------------------------------------
// Scratch (__device__ globals; allocation-free)
// q/k/v float [B,H,S,E]; packed bf16 hi/lo pair arrays for GEMM operands.
// Pair packing: uint32 = (bf16 of element k+1) << 16 | (bf16 of element k).
// ---------------------------------------------------------------------------
__device__ float    g_q[4194304];
__device__ float    g_k[4194304];
__device__ float    g_v[4194304];
__device__ uint32_t g_xh[2097152],  g_xl[2097152];   // x split:   [M][D/2]
__device__ uint32_t g_wth[1572864], g_wtl[1572864];  // W^T split: [3H][E][D/2]
__device__ uint32_t g_woth[524288], g_wotl[524288];  // Wo^T split:[1024][512]
__device__ uint32_t g_ah[2097152],  g_al[2097152];   // attn split:[M][512]

// ---------------------------------------------------------------------------
// Helpers
// ---------------------------------------------------------------------------
__device__ __forceinline__ void split2(float a, float b, uint32_t& hi, uint32_t& lo) {
    __nv_bfloat16 ha = __float2bfloat16(a);
    __nv_bfloat16 hb = __float2bfloat16(b);
    __nv_bfloat16 la = __float2bfloat16(a - __bfloat162float(ha));
    __nv_bfloat16 lb = __float2bfloat16(b - __bfloat162float(hb));
    hi = ((uint32_t)__bfloat16_as_ushort(hb) << 16) | (uint32_t)__bfloat16_as_ushort(ha);
    lo = ((uint32_t)__bfloat16_as_ushort(lb) << 16) | (uint32_t)__bfloat16_as_ushort(la);
}

__device__ __forceinline__ void mma_bf16(float d[4], const uint32_t a[4],
                                         uint32_t b0, uint32_t b1) {
    asm volatile(
        "mma.sync.aligned.m16n8k16.row.col.f32.bf16.bf16.f32 "
        "{%0,%1,%2,%3}, {%4,%5,%6,%7}, {%8,%9}, {%0,%1,%2,%3};"
        : "+f"(d[0]), "+f"(d[1]), "+f"(d[2]), "+f"(d[3])
        : "r"(a[0]), "r"(a[1]), "r"(a[2]), "r"(a[3]), "r"(b0), "r"(b1));
}

// ---------------------------------------------------------------------------
// Prep: split x into packed hi/lo pairs
// ---------------------------------------------------------------------------
__global__ void split_x_kernel(const float* __restrict__ x) {
    const int i = blockIdx.x * blockDim.x + threadIdx.x;   // one float4 each
    float4 v = ((const float4*)x)[i];
    uint32_t h0, l0, h1, l1;
    split2(v.x, v.y, h0, l0);
    split2(v.z, v.w, h1, l1);
    g_xh[2 * i] = h0; g_xh[2 * i + 1] = h1;
    g_xl[2 * i] = l0; g_xl[2 * i + 1] = l1;
}

// Wt[z][e][d-pairs] = split(W[z&7][d][e]); z = sel*8 + h
__global__ void transpose_w_kernel(const float* __restrict__ Wq,
                                   const float* __restrict__ Wk,
                                   const float* __restrict__ Wv) {
    const int z = blockIdx.z;
    const float* W = ((z < 8) ? Wq : (z < 16) ? Wk : Wv) + (size_t)(z & 7) * D_ * E_;
    __shared__ float tt[32][33];
    const int d0 = blockIdx.x * 32, e0 = blockIdx.y * 32;
    const int tx = threadIdx.x, ty = threadIdx.y;
#pragma unroll
    for (int i = 0; i < 32; i += 8)
        tt[ty + i][tx] = W[(size_t)(d0 + ty + i) * E_ + e0 + tx];   // tt[d][e]
    __syncthreads();
#pragma unroll
    for (int i = 0; i < 16; i += 8) {
        const int j = ty + i;                                       // pair index
        uint32_t hi, lo;
        split2(tt[2 * j][tx], tt[2 * j + 1][tx], hi, lo);
        const size_t off = ((size_t)z * E_ + e0 + tx) * 512 + (d0 >> 1) + j;
        g_wth[off] = hi;
        g_wtl[off] = lo;
    }
}

// Wot[n][k-pairs] = split(Wo[k][n])
__global__ void transpose_wo_kernel(const float* __restrict__ Wo) {
    __shared__ float tt[32][33];
    const int k0 = blockIdx.x * 32, n0 = blockIdx.y * 32;
    const int tx = threadIdx.x, ty = threadIdx.y;
#pragma unroll
    for (int i = 0; i < 32; i += 8)
        tt[ty + i][tx] = Wo[(size_t)(k0 + ty + i) * D_ + n0 + tx];  // tt[k][n]
    __syncthreads();
#pragma unroll
    for (int i = 0; i < 16; i += 8) {
        const int j = ty + i;
        uint32_t hi, lo;
        split2(tt[2 * j][tx], tt[2 * j + 1][tx], hi, lo);
        const size_t off = (size_t)(n0 + tx) * 512 + (k0 >> 1) + j;
        g_woth[off] = hi;
        g_wotl[off] = lo;
    }
}

// ---------------------------------------------------------------------------
// bf16x3 mma.sync GEMM: D[128,128] = A[128,1024] * Bt[128,1024]^T (+bias)
//   acc += Ah*Bh + Ah*Bl + Al*Bh   (fp32 accumulate; lo*lo dropped ~2^-16)
// mode 0: Q/K/V projections (grid 32 x 8 x 3); mode 1: out-proj (grid 32 x 8)
//
// Smem: packed k-pairs, [kp][m] with stride 136 (uint32) and column swizzle
//   col' = m ^ (((kp>>2)&3) << 3)
// Verified conflict-free for both the fill scatter and fragment loads.
// ---------------------------------------------------------------------------
#define SST 136

__global__ __launch_bounds__(256, 1) void gemm128_bf16(
    int mode,
    const float* __restrict__ bq, const float* __restrict__ bk,
    const float* __restrict__ bv, const float* __restrict__ bo,
    float* __restrict__ oout)
{
    __shared__ uint32_t Ash[16 * SST], Asl[16 * SST];
    __shared__ uint32_t Bsh[16 * SST], Bsl[16 * SST];

    const int tid  = threadIdx.x;
    const int wid  = tid >> 5;
    const int lane = tid & 31;
    const int g    = lane >> 2;      // 0..7
    const int t    = lane & 3;       // 0..3
    const int m0   = blockIdx.x * 128;
    const int mb   = (wid & 1) * 64;     // warp m-offset
    const int nb   = (wid >> 1) * 32;    // warp n-offset

    const uint32_t *Ah, *Al, *Bh, *Bl;
    const float* bias;
    if (mode == 0) {
        const int h = blockIdx.y, sel = blockIdx.z;
        Ah = g_xh + (size_t)m0 * 512;
        Al = g_xl + (size_t)m0 * 512;
        const size_t wo = (size_t)(sel * H_ + h) * E_ * 512;
        Bh = g_wth + wo;
        Bl = g_wtl + wo;
        bias = ((sel == 0) ? bq : (sel == 1) ? bk : bv) + h * E_;
    } else {
        Ah = g_ah + (size_t)m0 * 512;
        Al = g_al + (size_t)m0 * 512;
        const size_t wo = (size_t)blockIdx.y * 128 * 512;
        Bh = g_woth + wo;
        Bl = g_wotl + wo;
        bias = bo + blockIdx.y * 128;
    }

    float acc[4][4][4];
#pragma unroll
    for (int i = 0; i < 4; i++)
#pragma unroll
        for (int j = 0; j < 4; j++)
#pragma unroll
            for (int r = 0; r < 4; r++) acc[i][j][r] = 0.f;

    // fill mapping: uint4 id = u*256+tid -> row m = id>>2, kp-quad q = id&3
    int fm[2], fq[2];
#pragma unroll
    for (int u = 0; u < 2; u++) {
        const int id = u * 256 + tid;
        fm[u] = id >> 2;
        fq[u] = id & 3;
    }

    // prefetch chunk 0 (each uint4 = 4 packed pairs = 8 k-values)
    uint4 rah[2], ral[2], rbh[2], rbl[2];
#pragma unroll
    for (int u = 0; u < 2; u++) {
        const size_t ro = (size_t)fm[u] * 512 + 4 * fq[u];
        rah[u] = *(const uint4*)(Ah + ro);
        ral[u] = *(const uint4*)(Al + ro);
        rbh[u] = *(const uint4*)(Bh + ro);
        rbl[u] = *(const uint4*)(Bl + ro);
    }

    for (int i = 0; i < 32; i++) {
        __syncthreads();
        // scatter chunk i into smem (conflict-free)
#pragma unroll
        for (int u = 0; u < 2; u++) {
            const int col = fm[u] ^ (fq[u] << 3);
            const int rb  = 4 * fq[u] * SST + col;
            Ash[rb] = rah[u].x; Ash[rb + SST] = rah[u].y;
            Ash[rb + 2 * SST] = rah[u].z; Ash[rb + 3 * SST] = rah[u].w;
            Asl[rb] = ral[u].x; Asl[rb + SST] = ral[u].y;
            Asl[rb + 2 * SST] = ral[u].z; Asl[rb + 3 * SST] = ral[u].w;
            Bsh[rb] = rbh[u].x; Bsh[rb + SST] = rbh[u].y;
            Bsh[rb + 2 * SST] = rbh[u].z; Bsh[rb + 3 * SST] = rbh[u].w;
            Bsl[rb] = rbl[u].x; Bsl[rb + SST] = rbl[u].y;
            Bsl[rb + 2 * SST] = rbl[u].z; Bsl[rb + 3 * SST] = rbl[u].w;
        }
        // prefetch chunk i+1 (overlaps the mma section)
        if (i + 1 < 32) {
            const int kt = (i + 1) * 16;
#pragma unroll
            for (int u = 0; u < 2; u++) {
                const size_t ro = (size_t)fm[u] * 512 + kt + 4 * fq[u];
                rah[u] = *(const uint4*)(Ah + ro);
                ral[u] = *(const uint4*)(Al + ro);
                rbh[u] = *(const uint4*)(Bh + ro);
                rbl[u] = *(const uint4*)(Bl + ro);
            }
        }
        __syncthreads();

#pragma unroll
        for (int kk = 0; kk < 2; kk++) {
            const int r0 = (kk * 8 + t) * SST;       // kp = kk*8+t
            const int r1 = r0 + 4 * SST;             // kp = kk*8+t+4
            const int x0 = (kk * 2) << 3;            // swizzle for kp quad
            const int x1 = (kk * 2 + 1) << 3;

            uint32_t ah[4][4], al[4][4];
#pragma unroll
            for (int mt = 0; mt < 4; mt++) {
                const int c0 = mb + mt * 16 + g;
                const int c1 = c0 + 8;
                ah[mt][0] = Ash[r0 + (c0 ^ x0)];
                ah[mt][1] = Ash[r0 + (c1 ^ x0)];
                ah[mt][2] = Ash[r1 + (c0 ^ x1)];
                ah[mt][3] = Ash[r1 + (c1 ^ x1)];
                al[mt][0] = Asl[r0 + (c0 ^ x0)];
                al[mt][1] = Asl[r0 + (c1 ^ x0)];
                al[mt][2] = Asl[r1 + (c0 ^ x1)];
                al[mt][3] = Asl[r1 + (c1 ^ x1)];
            }
#pragma unroll
            for (int nt = 0; nt < 4; nt++) {
                const int cn = nb + nt * 8 + g;
                const uint32_t bh0 = Bsh[r0 + (cn ^ x0)];
                const uint32_t bh1 = Bsh[r1 + (cn ^ x1)];
                const uint32_t bl0 = Bsl[r0 + (cn ^ x0)];
                const uint32_t bl1 = Bsl[r1 + (cn ^ x1)];
#pragma unroll
                for (int mt = 0; mt < 4; mt++) {
                    mma_bf16(acc[mt][nt], ah[mt], bh0, bh1);
                    mma_bf16(acc[mt][nt], ah[mt], bl0, bl1);
                    mma_bf16(acc[mt][nt], al[mt], bh0, bh1);
                }
            }
        }
    }

    // epilogue: D element (row, col): row = mb+mt*16+g (+8), col = nb+nt*8+2t (+1)
    const int h = blockIdx.y, sel = blockIdx.z;
#pragma unroll
    for (int mt = 0; mt < 4; mt++) {
        const int m_lo = m0 + mb + mt * 16 + g;
#pragma unroll
        for (int rh = 0; rh < 2; rh++) {
            const int m = m_lo + rh * 8;
            float* dst;
            if (mode == 0) {
                const int bb = m >> 11;
                const int s  = m & (S_ - 1);
                float* out = (sel == 0) ? g_q : (sel == 1) ? g_k : g_v;
                dst = out + (((size_t)bb * H_ + h) * S_ + s) * E_;
            } else {
                dst = oout + (size_t)m * D_ + blockIdx.y * 128;
            }
#pragma unroll
            for (int nt = 0; nt < 4; nt++) {
                const int cn = nb + nt * 8 + 2 * t;
                float2 v;
                v.x = acc[mt][nt][2 * rh + 0] + bias[cn];
                v.y = acc[mt][nt][2 * rh + 1] + bias[cn + 1];
                *(float2*)(dst + cn) = v;
            }
        }
    }
}

// ---------------------------------------------------------------------------
// Windowed attention: one warp per (b, h, s) query.
// Output written split (hi/lo packed bf16 pairs) for the out-projection GEMM.
// ---------------------------------------------------------------------------
__global__ __launch_bounds__(256) void attn_kernel(
    const float* __restrict__ bk,
    const float* __restrict__ bv,
    const int*   __restrict__ dilations)
{
    const int warp = (blockIdx.x * blockDim.x + threadIdx.x) >> 5;
    const int lane = threadIdx.x & 31;
    const int s = warp & (S_ - 1);
    const int h = (warp >> 11) & (H_ - 1);
    const int b = warp >> 14;

    const int d = dilations[h];
    const int center = (d * (KW_ - 1)) >> 1;

    const size_t head_base = ((size_t)b * H_ + h) * S_ * E_;
    const float4 q4 = ((const float4*)(g_q + head_base + (size_t)s * E_))[lane];
    const float4* kbase = (const float4*)(g_k + head_base);
    const float4* vbase = (const float4*)(g_v + head_base);
    const float4 bk4 = ((const float4*)(bk + h * E_))[lane];
    const float4 bv4 = ((const float4*)(bv + h * E_))[lane];

    float logits[KW_];
    float4 vreg[KW_];

#pragma unroll
    for (int j = 0; j < KW_; j++) {
        const int pos = s + d * j - center;
        const bool ok = (pos >= 0) && (pos < S_);
        float4 k4;
        if (ok) {
            k4      = kbase[(size_t)pos * 32 + lane];
            vreg[j] = vbase[(size_t)pos * 32 + lane];
        } else {
            k4      = bk4;
            vreg[j] = bv4;
        }
        float p = k4.x * q4.x + k4.y * q4.y + k4.z * q4.z + k4.w * q4.w;
#pragma unroll
        for (int o = 16; o > 0; o >>= 1)
            p += __shfl_xor_sync(0xffffffffu, p, o);
        logits[j] = p;
    }

    float mx = logits[0];
#pragma unroll
    for (int j = 1; j < KW_; j++) mx = fmaxf(mx, logits[j]);
    float ssum = 0.f;
#pragma unroll
    for (int j = 0; j < KW_; j++) {
        logits[j] = __expf(logits[j] - mx);
        ssum += logits[j];
    }
    const float inv = 0.08838834764831845f / ssum;  // (1/sum) * (1/sqrt(E))

    float4 acc = make_float4(0.f, 0.f, 0.f, 0.f);
#pragma unroll
    for (int j = 0; j < KW_; j++) {
        const float w = logits[j] * inv;
        acc.x += w * vreg[j].x;
        acc.y += w * vreg[j].y;
        acc.z += w * vreg[j].z;
        acc.w += w * vreg[j].w;
    }

    // split-pack into [M][512] pair arrays; row = b*S+s, col pairs from h*64
    uint32_t h0, l0, h1, l1;
    split2(acc.x, acc.y, h0, l0);
    split2(acc.z, acc.w, h1, l1);
    const size_t off = (size_t)(b * S_ + s) * 512 + h * 64 + 2 * lane;
    g_ah[off] = h0; g_ah[off + 1] = h1;
    g_al[off] = l0; g_al[off + 1] = l1;
}

// ---------------------------------------------------------------------------
// Launch
// ---------------------------------------------------------------------------
extern "C" void kernel_launch(void* const* d_in, const int* in_sizes, int n_in,
                              void* d_out, int out_size)
{
    const float* x  = (const float*)d_in[0];
    const float* Wq = (const float*)d_in[1];
    const float* bq = (const float*)d_in[2];
    const float* Wk = (const float*)d_in[3];
    const float* bk = (const float*)d_in[4];
    const float* Wv = (const float*)d_in[5];
    const float* bv = (const float*)d_in[6];
    const float* Wo = (const float*)d_in[7];
    const float* bo = (const float*)d_in[8];
    const int*   dl = (const int*)d_in[9];
    float* out = (float*)d_out;

    // prep: split x and weights into bf16 hi/lo packed pairs
    split_x_kernel<<<(M_ * D_) / 4 / 256, 256>>>(x);
    transpose_w_kernel<<<dim3(D_ / 32, E_ / 32, 3 * H_), dim3(32, 8)>>>(Wq, Wk, Wv);
    transpose_wo_kernel<<<dim3(D_ / 32, D_ / 32), dim3(32, 8)>>>(Wo);

    // Q/K/V projections on tensor cores (bf16x3)
    gemm128_bf16<<<dim3(M_ / 128, H_, 3), 256>>>(0, bq, bk, bv, bo, out);

    // windowed attention
    attn_kernel<<<(B_ * H_ * S_) / 8, 256>>>(bk, bv, dl);

    // out-projection on tensor cores (bf16x3)
    gemm128_bf16<<<dim3(M_ / 128, D_ / 128, 1), 256>>>(1, bq, bk, bv, bo, out);
}

// round 11
// speedup vs baseline: 2.4595x; 1.2087x over previous
#include <cuda_runtime.h>
#include <cuda_bf16.h>
#include <cstdint>

#define B_  2
#define S_  2048
#define D_  1024
#define H_  8
#define E_  128
#define KW_ 16
#define M_  (B_ * S_)        // 4096 rows

// Tile-ready packed layout constants.
// A GEMM operand chunk = 128 rows x 16 k-pairs, stored as
//   [kl*136 + (row ^ ((kl>>2)<<3))]  (kl = kp & 15), hi then lo sub-block.
#define CH        2176          // uint32 per sub-block (16*136)
#define STG       8704          // uint32 per smem stage (Ah,Al,Bh,Bl)
#define STG_BYTES 34816
#define GEMM_SMEM (3 * STG_BYTES)   // 3-stage pipeline = 104448 B

// ---------------------------------------------------------------------------
// Scratch (__device__ globals; allocation-free)
// ---------------------------------------------------------------------------
__device__ float    g_q[4194304];        // [B,H,S,E]
__device__ float    g_k[4194304];
__device__ float    g_v[4194304];
__device__ uint32_t g_x2[4456448];       // x split:    [T=32][C=32][2][CH]
__device__ uint32_t g_w2[3342336];       // W^T split:  [z=24][C=32][2][CH]
__device__ uint32_t g_wo2[1114112];      // Wo^T split: [nt=8][C=32][2][CH]
__device__ uint32_t g_a2[4456448];       // attn split: [T=32][C=32][2][CH]

// ---------------------------------------------------------------------------
// Helpers
// ---------------------------------------------------------------------------
__device__ __forceinline__ void split2(float a, float b, uint32_t& hi, uint32_t& lo) {
    __nv_bfloat16 ha = __float2bfloat16(a);
    __nv_bfloat16 hb = __float2bfloat16(b);
    __nv_bfloat16 la = __float2bfloat16(a - __bfloat162float(ha));
    __nv_bfloat16 lb = __float2bfloat16(b - __bfloat162float(hb));
    hi = ((uint32_t)__bfloat16_as_ushort(hb) << 16) | (uint32_t)__bfloat16_as_ushort(ha);
    lo = ((uint32_t)__bfloat16_as_ushort(lb) << 16) | (uint32_t)__bfloat16_as_ushort(la);
}

__device__ __forceinline__ void mma_bf16(float d[4], const uint32_t a[4],
                                         uint32_t b0, uint32_t b1) {
    asm volatile(
        "mma.sync.aligned.m16n8k16.row.col.f32.bf16.bf16.f32 "
        "{%0,%1,%2,%3}, {%4,%5,%6,%7}, {%8,%9}, {%0,%1,%2,%3};"
        : "+f"(d[0]), "+f"(d[1]), "+f"(d[2]), "+f"(d[3])
        : "r"(a[0]), "r"(a[1]), "r"(a[2]), "r"(a[3]), "r"(b0), "r"(b1));
}

__device__ __forceinline__ uint32_t smem_u32(const void* p) {
    uint32_t a;
    asm("{ .reg .u64 t; cvta.to.shared.u64 t, %1; cvt.u32.u64 %0, t; }" : "=r"(a) : "l"(p));
    return a;
}

#define CP16(dst, src) \
    asm volatile("cp.async.cg.shared.global [%0], [%1], 16;" :: "r"(dst), "l"(src))
#define CPCOMMIT() asm volatile("cp.async.commit_group;" ::: "memory")
#define CPWAIT1()  asm volatile("cp.async.wait_group 1;"  ::: "memory")

// tile offset inside a sub-block: row 0..127, kl 0..15
__device__ __forceinline__ int toff(int row, int kl) {
    return kl * 136 + (row ^ ((kl >> 2) << 3));
}

// ---------------------------------------------------------------------------
// Prep: split x into tile-ready packed hi/lo blocks
// ---------------------------------------------------------------------------
__global__ void split_x_kernel(const float* __restrict__ x) {
    const int i = blockIdx.x * blockDim.x + threadIdx.x;   // one float4 each
    float4 v = ((const float4*)x)[i];
    const int m = i >> 8;            // row (D/4 = 256 float4 per row)
    const int c = i & 255;
    const int T = m >> 7, mloc = m & 127;
    const int kp0 = 2 * c;
    const int C = kp0 >> 4;
    const int kl0 = kp0 & 15, kl1 = kl0 + 1;   // same chunk (kp0 even)
    uint32_t* base = g_x2 + ((size_t)(T * 32 + C) * 2) * CH;
    uint32_t h0, l0, h1, l1;
    split2(v.x, v.y, h0, l0);
    split2(v.z, v.w, h1, l1);
    base[toff(mloc, kl0)]      = h0;
    base[toff(mloc, kl1)]      = h1;
    base[CH + toff(mloc, kl0)] = l0;
    base[CH + toff(mloc, kl1)] = l1;
}

// W^T tile blocks: z = sel*8 + h; tile rows = e (0..127), k = d
__global__ void transpose_w_kernel(const float* __restrict__ Wq,
                                   const float* __restrict__ Wk,
                                   const float* __restrict__ Wv) {
    const int z = blockIdx.z;
    const float* W = ((z < 8) ? Wq : (z < 16) ? Wk : Wv) + (size_t)(z & 7) * D_ * E_;
    __shared__ float tt[32][33];
    const int d0 = blockIdx.x * 32, e0 = blockIdx.y * 32;
    const int tx = threadIdx.x, ty = threadIdx.y;
#pragma unroll
    for (int i = 0; i < 32; i += 8)
        tt[ty + i][tx] = W[(size_t)(d0 + ty + i) * E_ + e0 + tx];   // tt[d][e]
    __syncthreads();
    uint32_t* base = g_w2 + ((size_t)(z * 32 + (d0 >> 5)) * 2) * CH;
    const int e = e0 + tx;
#pragma unroll
    for (int i = 0; i < 16; i += 8) {
        const int j = ty + i;                 // kl 0..15
        uint32_t hi, lo;
        split2(tt[2 * j][tx], tt[2 * j + 1][tx], hi, lo);
        base[toff(e, j)]      = hi;
        base[CH + toff(e, j)] = lo;
    }
}

// Wo^T tile blocks: tile rows = n (output dim), k = h*E+e
__global__ void transpose_wo_kernel(const float* __restrict__ Wo) {
    __shared__ float tt[32][33];
    const int k0 = blockIdx.x * 32, n0 = blockIdx.y * 32;
    const int tx = threadIdx.x, ty = threadIdx.y;
#pragma unroll
    for (int i = 0; i < 32; i += 8)
        tt[ty + i][tx] = Wo[(size_t)(k0 + ty + i) * D_ + n0 + tx];  // tt[k][n]
    __syncthreads();
    const int n = n0 + tx;
    const int nt = n >> 7, nloc = n & 127;
    uint32_t* base = g_wo2 + ((size_t)(nt * 32 + (k0 >> 5)) * 2) * CH;
#pragma unroll
    for (int i = 0; i < 16; i += 8) {
        const int j = ty + i;
        uint32_t hi, lo;
        split2(tt[2 * j][tx], tt[2 * j + 1][tx], hi, lo);
        base[toff(nloc, j)]      = hi;
        base[CH + toff(nloc, j)] = lo;
    }
}

// ---------------------------------------------------------------------------
// bf16x3 mma.sync GEMM with cp.async 3-stage pipeline.
//   D[128,128] = A[128,1024] * Bt[128,1024]^T (+bias)
//   acc += Ah*Bh + Ah*Bl + Al*Bh   (fp32 accumulate)
// Global operands are pre-packed in smem tile format -> identity cp.async.
// mode 0: Q/K/V projections (grid 32 x 8 x 3); mode 1: out-proj (grid 32 x 8)
// ---------------------------------------------------------------------------
__global__ __launch_bounds__(256, 1) void gemm128_bf16(
    int mode,
    const float* __restrict__ bq, const float* __restrict__ bk,
    const float* __restrict__ bv, const float* __restrict__ bo,
    float* __restrict__ oout)
{
    extern __shared__ uint32_t dyn[];
    const uint32_t sb = smem_u32(dyn);

    const int tid  = threadIdx.x;
    const int wid  = tid >> 5;
    const int lane = tid & 31;
    const int g    = lane >> 2;      // 0..7
    const int t    = lane & 3;       // 0..3
    const int m0   = blockIdx.x * 128;
    const int mb   = (wid & 1) * 64;     // warp m-offset
    const int nb   = (wid >> 1) * 32;    // warp n-offset

    const uint32_t *Asrc, *Bsrc;
    const float* bias;
    if (mode == 0) {
        const int h = blockIdx.y, sel = blockIdx.z;
        Asrc = g_x2 + ((size_t)blockIdx.x * 32 * 2) * CH;
        Bsrc = g_w2 + ((size_t)(sel * H_ + h) * 32 * 2) * CH;
        bias = ((sel == 0) ? bq : (sel == 1) ? bk : bv) + h * E_;
    } else {
        Asrc = g_a2  + ((size_t)blockIdx.x * 32 * 2) * CH;
        Bsrc = g_wo2 + ((size_t)blockIdx.y * 32 * 2) * CH;
        bias = bo + blockIdx.y * 128;
    }

    float acc[4][4][4];
#pragma unroll
    for (int i = 0; i < 4; i++)
#pragma unroll
        for (int j = 0; j < 4; j++)
#pragma unroll
            for (int r = 0; r < 4; r++) acc[i][j][r] = 0.f;

    // issue chunk c into stage st (identity copy, 2*CH uint32 per operand)
    auto issue = [&](int c, int st) {
        const uint32_t dA = sb + st * STG_BYTES;
        const char* sA = (const char*)(Asrc + (size_t)c * 2 * CH);
        const char* sB = (const char*)(Bsrc + (size_t)c * 2 * CH);
#pragma unroll
        for (int j = 0; j < 5; j++) {
            const int v = j * 256 + tid;
            if (j < 4 || v < 1088) {
                CP16(dA + v * 16,         sA + v * 16);
                CP16(dA + 17408 + v * 16, sB + v * 16);
            }
        }
    };

    issue(0, 0); CPCOMMIT();
    issue(1, 1); CPCOMMIT();

    for (int i = 0; i < 32; i++) {
        CPWAIT1();            // chunk i resident (own groups), then publish
        __syncthreads();      // all threads' chunk-i copies visible; prior reads done
        if (i + 2 < 32) issue(i + 2, (i + 2) % 3);
        CPCOMMIT();           // always commit (possibly empty) to keep group count

        const uint32_t* Ash = dyn + (i % 3) * STG;
        const uint32_t* Asl = Ash + CH;
        const uint32_t* Bsh = Ash + 2 * CH;
        const uint32_t* Bsl = Ash + 3 * CH;

#pragma unroll
        for (int kk = 0; kk < 2; kk++) {
            const int r0 = (kk * 8 + t) * 136;       // kp = kk*8+t
            const int r1 = r0 + 4 * 136;             // kp = kk*8+t+4
            const int x0 = (kk * 2) << 3;            // swizzle for kp quad
            const int x1 = (kk * 2 + 1) << 3;

            uint32_t ah[4][4], al[4][4];
#pragma unroll
            for (int mt = 0; mt < 4; mt++) {
                const int c0 = mb + mt * 16 + g;
                const int c1 = c0 + 8;
                ah[mt][0] = Ash[r0 + (c0 ^ x0)];
                ah[mt][1] = Ash[r0 + (c1 ^ x0)];
                ah[mt][2] = Ash[r1 + (c0 ^ x1)];
                ah[mt][3] = Ash[r1 + (c1 ^ x1)];
                al[mt][0] = Asl[r0 + (c0 ^ x0)];
                al[mt][1] = Asl[r0 + (c1 ^ x0)];
                al[mt][2] = Asl[r1 + (c0 ^ x1)];
                al[mt][3] = Asl[r1 + (c1 ^ x1)];
            }
#pragma unroll
            for (int nt = 0; nt < 4; nt++) {
                const int cn = nb + nt * 8 + g;
                const uint32_t bh0 = Bsh[r0 + (cn ^ x0)];
                const uint32_t bh1 = Bsh[r1 + (cn ^ x1)];
                const uint32_t bl0 = Bsl[r0 + (cn ^ x0)];
                const uint32_t bl1 = Bsl[r1 + (cn ^ x1)];
#pragma unroll
                for (int mt = 0; mt < 4; mt++) {
                    mma_bf16(acc[mt][nt], ah[mt], bh0, bh1);
                    mma_bf16(acc[mt][nt], ah[mt], bl0, bl1);
                    mma_bf16(acc[mt][nt], al[mt], bh0, bh1);
                }
            }
        }
    }

    // epilogue: D element (row, col): row = mb+mt*16+g (+8), col = nb+nt*8+2t (+1)
    const int h = blockIdx.y, sel = blockIdx.z;
#pragma unroll
    for (int mt = 0; mt < 4; mt++) {
        const int m_lo = m0 + mb + mt * 16 + g;
#pragma unroll
        for (int rh = 0; rh < 2; rh++) {
            const int m = m_lo + rh * 8;
            float* dst;
            if (mode == 0) {
                const int bb = m >> 11;
                const int s  = m & (S_ - 1);
                float* out = (sel == 0) ? g_q : (sel == 1) ? g_k : g_v;
                dst = out + (((size_t)bb * H_ + h) * S_ + s) * E_;
            } else {
                dst = oout + (size_t)m * D_ + blockIdx.y * 128;
            }
#pragma unroll
            for (int nt = 0; nt < 4; nt++) {
                const int cn = nb + nt * 8 + 2 * t;
                float2 v;
                v.x = acc[mt][nt][2 * rh + 0] + bias[cn];
                v.y = acc[mt][nt][2 * rh + 1] + bias[cn + 1];
                *(float2*)(dst + cn) = v;
            }
        }
    }
}

// ---------------------------------------------------------------------------
// Windowed attention: one warp per (b, h, s) query.
// Output written split into tile-ready blocks for the out-projection GEMM.
// ---------------------------------------------------------------------------
__global__ __launch_bounds__(256) void attn_kernel(
    const float* __restrict__ bk,
    const float* __restrict__ bv,
    const int*   __restrict__ dilations)
{
    const int warp = (blockIdx.x * blockDim.x + threadIdx.x) >> 5;
    const int lane = threadIdx.x & 31;
    const int s = warp & (S_ - 1);
    const int h = (warp >> 11) & (H_ - 1);
    const int b = warp >> 14;

    const int d = dilations[h];
    const int center = (d * (KW_ - 1)) >> 1;

    const size_t head_base = ((size_t)b * H_ + h) * S_ * E_;
    const float4 q4 = ((const float4*)(g_q + head_base + (size_t)s * E_))[lane];
    const float4* kbase = (const float4*)(g_k + head_base);
    const float4* vbase = (const float4*)(g_v + head_base);
    const float4 bk4 = ((const float4*)(bk + h * E_))[lane];
    const float4 bv4 = ((const float4*)(bv + h * E_))[lane];

    float logits[KW_];
    float4 vreg[KW_];

#pragma unroll
    for (int j = 0; j < KW_; j++) {
        const int pos = s + d * j - center;
        const bool ok = (pos >= 0) && (pos < S_);
        float4 k4;
        if (ok) {
            k4      = kbase[(size_t)pos * 32 + lane];
            vreg[j] = vbase[(size_t)pos * 32 + lane];
        } else {
            k4      = bk4;
            vreg[j] = bv4;
        }
        float p = k4.x * q4.x + k4.y * q4.y + k4.z * q4.z + k4.w * q4.w;
#pragma unroll
        for (int o = 16; o > 0; o >>= 1)
            p += __shfl_xor_sync(0xffffffffu, p, o);
        logits[j] = p;
    }

    float mx = logits[0];
#pragma unroll
    for (int j = 1; j < KW_; j++) mx = fmaxf(mx, logits[j]);
    float ssum = 0.f;
#pragma unroll
    for (int j = 0; j < KW_; j++) {
        logits[j] = __expf(logits[j] - mx);
        ssum += logits[j];
    }
    const float inv = 0.08838834764831845f / ssum;  // (1/sum) * (1/sqrt(E))

    float4 acc = make_float4(0.f, 0.f, 0.f, 0.f);
#pragma unroll
    for (int j = 0; j < KW_; j++) {
        const float w = logits[j] * inv;
        acc.x += w * vreg[j].x;
        acc.y += w * vreg[j].y;
        acc.z += w * vreg[j].z;
        acc.w += w * vreg[j].w;
    }

    // split-pack into tile-ready blocks; row m = b*S+s, k = h*E + 4*lane..+3
    const int m = b * S_ + s;
    const int T = m >> 7, mloc = m & 127;
    const int kp0 = h * 64 + 2 * lane;       // two consecutive kp, same chunk
    const int C = kp0 >> 4;
    const int kl0 = kp0 & 15, kl1 = kl0 + 1;
    uint32_t* base = g_a2 + ((size_t)(T * 32 + C) * 2) * CH;
    uint32_t h0, l0, h1, l1;
    split2(acc.x, acc.y, h0, l0);
    split2(acc.z, acc.w, h1, l1);
    base[toff(mloc, kl0)]      = h0;
    base[toff(mloc, kl1)]      = h1;
    base[CH + toff(mloc, kl0)] = l0;
    base[CH + toff(mloc, kl1)] = l1;
}

// ---------------------------------------------------------------------------
// Launch
// ---------------------------------------------------------------------------
extern "C" void kernel_launch(void* const* d_in, const int* in_sizes, int n_in,
                              void* d_out, int out_size)
{
    const float* x  = (const float*)d_in[0];
    const float* Wq = (const float*)d_in[1];
    const float* bq = (const float*)d_in[2];
    const float* Wk = (const float*)d_in[3];
    const float* bk = (const float*)d_in[4];
    const float* Wv = (const float*)d_in[5];
    const float* bv = (const float*)d_in[6];
    const float* Wo = (const float*)d_in[7];
    const float* bo = (const float*)d_in[8];
    const int*   dl = (const int*)d_in[9];
    float* out = (float*)d_out;

    // Not a stream op; graph-capture safe. Unconditional (no static guards).
    cudaFuncSetAttribute(gemm128_bf16, cudaFuncAttributeMaxDynamicSharedMemorySize, GEMM_SMEM);

    // prep: split operands into tile-ready bf16 hi/lo blocks
    split_x_kernel<<<(M_ * D_) / 4 / 256, 256>>>(x);
    transpose_w_kernel<<<dim3(D_ / 32, E_ / 32, 3 * H_), dim3(32, 8)>>>(Wq, Wk, Wv);
    transpose_wo_kernel<<<dim3(D_ / 32, D_ / 32), dim3(32, 8)>>>(Wo);

    // Q/K/V projections on tensor cores (bf16x3)
    gemm128_bf16<<<dim3(M_ / 128, H_, 3), 256, GEMM_SMEM>>>(0, bq, bk, bv, bo, out);

    // windowed attention
    attn_kernel<<<(B_ * H_ * S_) / 8, 256>>>(bk, bv, dl);

    // out-projection on tensor cores (bf16x3)
    gemm128_bf16<<<dim3(M_ / 128, D_ / 128, 1), 256, GEMM_SMEM>>>(1, bq, bk, bv, bo, out);
}

// round 13
// speedup vs baseline: 2.5506x; 1.0371x over previous
#include <cuda_runtime.h>
#include <cuda_bf16.h>
#include <cstdint>

#define B_  2
#define S_  2048
#define D_  1024
#define H_  8
#define E_  128
#define KW_ 16
#define M_  (B_ * S_)        // 4096 rows

// Tile-ready packed layout constants.
// A GEMM operand chunk = 128 rows x 16 k-pairs, stored as
//   [kl*136 + (row ^ ((kl>>2)<<3))]  (kl = kp & 15), hi then lo sub-block.
#define CH        2176          // uint32 per sub-block (16*136)
#define STG       8704          // uint32 per smem stage (Ah,Al,Bh,Bl)
#define STG_BYTES 34816
#define GEMM_SMEM (3 * STG_BYTES)   // 3-stage pipeline = 104448 B (x2 CTAs fits)

// ---------------------------------------------------------------------------
// Scratch (__device__ globals; allocation-free). Only referenced from device
// code — NEVER passed as kernel arguments from host (host shadow != dev addr).
// ---------------------------------------------------------------------------
__device__ float    g_q[4194304];        // [B,H,S,E]
__device__ float    g_k[4194304];
__device__ float    g_v[4194304];
__device__ float    g_attn[4194304];     // [B,S,H,E] float (attn output)
__device__ uint32_t g_x2[4456448];       // x split:    [T=32][C=32][2][CH]
__device__ uint32_t g_w2[3342336];       // W^T split:  [z=24][C=32][2][CH]
__device__ uint32_t g_wo2[1114112];      // Wo^T split: [nt=8][C=32][2][CH]
__device__ uint32_t g_a2[4456448];       // attn split: [T=32][C=32][2][CH]

// ---------------------------------------------------------------------------
// Helpers
// ---------------------------------------------------------------------------
__device__ __forceinline__ void split2(float a, float b, uint32_t& hi, uint32_t& lo) {
    __nv_bfloat16 ha = __float2bfloat16(a);
    __nv_bfloat16 hb = __float2bfloat16(b);
    __nv_bfloat16 la = __float2bfloat16(a - __bfloat162float(ha));
    __nv_bfloat16 lb = __float2bfloat16(b - __bfloat162float(hb));
    hi = ((uint32_t)__bfloat16_as_ushort(hb) << 16) | (uint32_t)__bfloat16_as_ushort(ha);
    lo = ((uint32_t)__bfloat16_as_ushort(lb) << 16) | (uint32_t)__bfloat16_as_ushort(la);
}

__device__ __forceinline__ void mma_bf16(float d[4], const uint32_t a[4],
                                         uint32_t b0, uint32_t b1) {
    asm volatile(
        "mma.sync.aligned.m16n8k16.row.col.f32.bf16.bf16.f32 "
        "{%0,%1,%2,%3}, {%4,%5,%6,%7}, {%8,%9}, {%0,%1,%2,%3};"
        : "+f"(d[0]), "+f"(d[1]), "+f"(d[2]), "+f"(d[3])
        : "r"(a[0]), "r"(a[1]), "r"(a[2]), "r"(a[3]), "r"(b0), "r"(b1));
}

__device__ __forceinline__ uint32_t smem_u32(const void* p) {
    uint32_t a;
    asm("{ .reg .u64 t; cvta.to.shared.u64 t, %1; cvt.u32.u64 %0, t; }" : "=r"(a) : "l"(p));
    return a;
}

#define CP16(dst, src) \
    asm volatile("cp.async.cg.shared.global [%0], [%1], 16;" :: "r"(dst), "l"(src))
#define CPCOMMIT() asm volatile("cp.async.commit_group;" ::: "memory")
#define CPWAIT1()  asm volatile("cp.async.wait_group 1;"  ::: "memory")

// tile offset inside a sub-block: row 0..127, kl 0..15
__device__ __forceinline__ int toff(int row, int kl) {
    return kl * 136 + (row ^ ((kl >> 2) << 3));
}

// ---------------------------------------------------------------------------
// split_tile: [4096 x 1024] fp32 row-major -> tile-ready hi/lo packed blocks.
// which==0: src = x (kernel arg), dst = g_x2
// which==1: src = g_attn,         dst = g_a2
// grid (C=32, T=32), 256 threads. Coalesced global reads AND writes.
// ---------------------------------------------------------------------------
__global__ __launch_bounds__(256) void split_tile(int which,
                                                  const float* __restrict__ xsrc)
{
    const float*   src = (which == 0) ? xsrc : g_attn;
    uint32_t*      dst = (which == 0) ? g_x2 : g_a2;

    __shared__ float s[128][33];
    const int C = blockIdx.x, T = blockIdx.y;
    const int tid  = threadIdx.x;
    const int wid  = tid >> 5;
    const int lane = tid & 31;

#pragma unroll
    for (int it = 0; it < 4; it++) {
        const int v  = it * 256 + tid;          // 0..1023 float4 slots
        const int r  = v >> 3;
        const int c4 = (v & 7) * 4;
        float4 x4 = *(const float4*)(src + (size_t)(T * 128 + r) * 1024 + C * 32 + c4);
        s[r][c4 + 0] = x4.x; s[r][c4 + 1] = x4.y;
        s[r][c4 + 2] = x4.z; s[r][c4 + 3] = x4.w;
    }
    __syncthreads();

    uint32_t* base = dst + ((size_t)(T * 32 + C) * 2) * CH;
#pragma unroll
    for (int itt = 0; itt < 8; itt++) {
        const int task = itt * 8 + wid;         // 64 tasks
        const int kl = task >> 2;               // 0..15
        const int rg = task & 3;                // row group of 32
        const int sw = (kl >> 2) << 3;
        const int rowp = rg * 32 + lane;        // output word index within kl
        const int r = rowp ^ sw;                // source row
        uint32_t hi, lo;
        split2(s[r][2 * kl], s[r][2 * kl + 1], hi, lo);
        base[kl * 136 + rowp]      = hi;
        base[CH + kl * 136 + rowp] = lo;
    }
}

// W^T tile blocks: z = sel*8 + h; tile rows = e (0..127), k = d
__global__ void transpose_w_kernel(const float* __restrict__ Wq,
                                   const float* __restrict__ Wk,
                                   const float* __restrict__ Wv) {
    const int z = blockIdx.z;
    const float* W = ((z < 8) ? Wq : (z < 16) ? Wk : Wv) + (size_t)(z & 7) * D_ * E_;
    __shared__ float tt[32][33];
    const int d0 = blockIdx.x * 32, e0 = blockIdx.y * 32;
    const int tx = threadIdx.x, ty = threadIdx.y;
#pragma unroll
    for (int i = 0; i < 32; i += 8)
        tt[ty + i][tx] = W[(size_t)(d0 + ty + i) * E_ + e0 + tx];   // tt[d][e]
    __syncthreads();
    uint32_t* base = g_w2 + ((size_t)(z * 32 + (d0 >> 5)) * 2) * CH;
    const int e = e0 + tx;
#pragma unroll
    for (int i = 0; i < 16; i += 8) {
        const int j = ty + i;                 // kl 0..15
        uint32_t hi, lo;
        split2(tt[2 * j][tx], tt[2 * j + 1][tx], hi, lo);
        base[toff(e, j)]      = hi;
        base[CH + toff(e, j)] = lo;
    }
}

// Wo^T tile blocks: tile rows = n (output dim), k = h*E+e
__global__ void transpose_wo_kernel(const float* __restrict__ Wo) {
    __shared__ float tt[32][33];
    const int k0 = blockIdx.x * 32, n0 = blockIdx.y * 32;
    const int tx = threadIdx.x, ty = threadIdx.y;
#pragma unroll
    for (int i = 0; i < 32; i += 8)
        tt[ty + i][tx] = Wo[(size_t)(k0 + ty + i) * D_ + n0 + tx];  // tt[k][n]
    __syncthreads();
    const int n = n0 + tx;
    const int nt = n >> 7, nloc = n & 127;
    uint32_t* base = g_wo2 + ((size_t)(nt * 32 + (k0 >> 5)) * 2) * CH;
#pragma unroll
    for (int i = 0; i < 16; i += 8) {
        const int j = ty + i;
        uint32_t hi, lo;
        split2(tt[2 * j][tx], tt[2 * j + 1][tx], hi, lo);
        base[toff(nloc, j)]      = hi;
        base[CH + toff(nloc, j)] = lo;
    }
}

// ---------------------------------------------------------------------------
// bf16x3 mma.sync GEMM with cp.async 3-stage pipeline, 2 CTAs/SM.
//   D[128,128] = A[128,1024] * Bt[128,1024]^T (+bias)
//   acc += Ah*Bh + Ah*Bl + Al*Bh   (fp32 accumulate)
// mode 0: Q/K/V projections (grid 32 x 8 x 3); mode 1: out-proj (grid 32 x 8)
// ---------------------------------------------------------------------------
__global__ __launch_bounds__(256, 2) void gemm128_bf16(
    int mode,
    const float* __restrict__ bq, const float* __restrict__ bk,
    const float* __restrict__ bv, const float* __restrict__ bo,
    float* __restrict__ oout)
{
    extern __shared__ uint32_t dyn[];
    const uint32_t sb = smem_u32(dyn);

    const int tid  = threadIdx.x;
    const int wid  = tid >> 5;
    const int lane = tid & 31;
    const int g    = lane >> 2;      // 0..7
    const int t    = lane & 3;       // 0..3
    const int m0   = blockIdx.x * 128;
    const int mb   = (wid & 1) * 64;     // warp m-offset
    const int nb   = (wid >> 1) * 32;    // warp n-offset

    const uint32_t *Asrc, *Bsrc;
    const float* bias;
    if (mode == 0) {
        const int h = blockIdx.y, sel = blockIdx.z;
        Asrc = g_x2 + ((size_t)blockIdx.x * 32 * 2) * CH;
        Bsrc = g_w2 + ((size_t)(sel * H_ + h) * 32 * 2) * CH;
        bias = ((sel == 0) ? bq : (sel == 1) ? bk : bv) + h * E_;
    } else {
        Asrc = g_a2  + ((size_t)blockIdx.x * 32 * 2) * CH;
        Bsrc = g_wo2 + ((size_t)blockIdx.y * 32 * 2) * CH;
        bias = bo + blockIdx.y * 128;
    }

    float acc[4][4][4];
#pragma unroll
    for (int i = 0; i < 4; i++)
#pragma unroll
        for (int j = 0; j < 4; j++)
#pragma unroll
            for (int r = 0; r < 4; r++) acc[i][j][r] = 0.f;

    // issue chunk c into stage st (identity copy, 2*CH uint32 per operand)
    auto issue = [&](int c, int st) {
        const uint32_t dA = sb + st * STG_BYTES;
        const char* sA = (const char*)(Asrc + (size_t)c * 2 * CH);
        const char* sB = (const char*)(Bsrc + (size_t)c * 2 * CH);
#pragma unroll
        for (int j = 0; j < 5; j++) {
            const int v = j * 256 + tid;
            if (j < 4 || v < 1088) {
                CP16(dA + v * 16,         sA + v * 16);
                CP16(dA + 17408 + v * 16, sB + v * 16);
            }
        }
    };

    issue(0, 0); CPCOMMIT();
    issue(1, 1); CPCOMMIT();

    for (int i = 0; i < 32; i++) {
        CPWAIT1();            // chunk i resident (own groups), then publish
        __syncthreads();      // all threads' chunk-i copies visible; prior reads done
        if (i + 2 < 32) issue(i + 2, (i + 2) % 3);
        CPCOMMIT();           // always commit (possibly empty) to keep group count

        const uint32_t* Ash = dyn + (i % 3) * STG;
        const uint32_t* Asl = Ash + CH;
        const uint32_t* Bsh = Ash + 2 * CH;
        const uint32_t* Bsl = Ash + 3 * CH;

#pragma unroll
        for (int kk = 0; kk < 2; kk++) {
            const int r0 = (kk * 8 + t) * 136;       // kp = kk*8+t
            const int r1 = r0 + 4 * 136;             // kp = kk*8+t+4
            const int x0 = (kk * 2) << 3;            // swizzle for kp quad
            const int x1 = (kk * 2 + 1) << 3;

            uint32_t ah[4][4], al[4][4];
#pragma unroll
            for (int mt = 0; mt < 4; mt++) {
                const int c0 = mb + mt * 16 + g;
                const int c1 = c0 + 8;
                ah[mt][0] = Ash[r0 + (c0 ^ x0)];
                ah[mt][1] = Ash[r0 + (c1 ^ x0)];
                ah[mt][2] = Ash[r1 + (c0 ^ x1)];
                ah[mt][3] = Ash[r1 + (c1 ^ x1)];
                al[mt][0] = Asl[r0 + (c0 ^ x0)];
                al[mt][1] = Asl[r0 + (c1 ^ x0)];
                al[mt][2] = Asl[r1 + (c0 ^ x1)];
                al[mt][3] = Asl[r1 + (c1 ^ x1)];
            }
#pragma unroll
            for (int nt = 0; nt < 4; nt++) {
                const int cn = nb + nt * 8 + g;
                const uint32_t bh0 = Bsh[r0 + (cn ^ x0)];
                const uint32_t bh1 = Bsh[r1 + (cn ^ x1)];
                const uint32_t bl0 = Bsl[r0 + (cn ^ x0)];
                const uint32_t bl1 = Bsl[r1 + (cn ^ x1)];
#pragma unroll
                for (int mt = 0; mt < 4; mt++) {
                    mma_bf16(acc[mt][nt], ah[mt], bh0, bh1);
                    mma_bf16(acc[mt][nt], ah[mt], bl0, bl1);
                    mma_bf16(acc[mt][nt], al[mt], bh0, bh1);
                }
            }
        }
    }

    // epilogue: D element (row, col): row = mb+mt*16+g (+8), col = nb+nt*8+2t (+1)
    const int h = blockIdx.y, sel = blockIdx.z;
#pragma unroll
    for (int mt = 0; mt < 4; mt++) {
        const int m_lo = m0 + mb + mt * 16 + g;
#pragma unroll
        for (int rh = 0; rh < 2; rh++) {
            const int m = m_lo + rh * 8;
            float* dst;
            if (mode == 0) {
                const int bb = m >> 11;
                const int s  = m & (S_ - 1);
                float* out = (sel == 0) ? g_q : (sel == 1) ? g_k : g_v;
                dst = out + (((size_t)bb * H_ + h) * S_ + s) * E_;
            } else {
                dst = oout + (size_t)m * D_ + blockIdx.y * 128;
            }
#pragma unroll
            for (int nt = 0; nt < 4; nt++) {
                const int cn = nb + nt * 8 + 2 * t;
                float2 v;
                v.x = acc[mt][nt][2 * rh + 0] + bias[cn];
                v.y = acc[mt][nt][2 * rh + 1] + bias[cn + 1];
                *(float2*)(dst + cn) = v;
            }
        }
    }
}

// ---------------------------------------------------------------------------
// Windowed attention: one warp per (b, h, s) query.
// Output: plain float [B,S,H,E] (coalesced); repacked by split_tile after.
// ---------------------------------------------------------------------------
__global__ __launch_bounds__(256) void attn_kernel(
    const float* __restrict__ bk,
    const float* __restrict__ bv,
    const int*   __restrict__ dilations)
{
    const int warp = (blockIdx.x * blockDim.x + threadIdx.x) >> 5;
    const int lane = threadIdx.x & 31;
    const int s = warp & (S_ - 1);
    const int h = (warp >> 11) & (H_ - 1);
    const int b = warp >> 14;

    const int d = dilations[h];
    const int center = (d * (KW_ - 1)) >> 1;

    const size_t head_base = ((size_t)b * H_ + h) * S_ * E_;
    const float4 q4 = ((const float4*)(g_q + head_base + (size_t)s * E_))[lane];
    const float4* kbase = (const float4*)(g_k + head_base);
    const float4* vbase = (const float4*)(g_v + head_base);
    const float4 bk4 = ((const float4*)(bk + h * E_))[lane];
    const float4 bv4 = ((const float4*)(bv + h * E_))[lane];

    float logits[KW_];
    float4 vreg[KW_];

#pragma unroll
    for (int j = 0; j < KW_; j++) {
        const int pos = s + d * j - center;
        const bool ok = (pos >= 0) && (pos < S_);
        float4 k4;
        if (ok) {
            k4      = kbase[(size_t)pos * 32 + lane];
            vreg[j] = vbase[(size_t)pos * 32 + lane];
        } else {
            k4      = bk4;
            vreg[j] = bv4;
        }
        float p = k4.x * q4.x + k4.y * q4.y + k4.z * q4.z + k4.w * q4.w;
#pragma unroll
        for (int o = 16; o > 0; o >>= 1)
            p += __shfl_xor_sync(0xffffffffu, p, o);
        logits[j] = p;
    }

    float mx = logits[0];
#pragma unroll
    for (int j = 1; j < KW_; j++) mx = fmaxf(mx, logits[j]);
    float ssum = 0.f;
#pragma unroll
    for (int j = 0; j < KW_; j++) {
        logits[j] = __expf(logits[j] - mx);
        ssum += logits[j];
    }
    const float inv = 0.08838834764831845f / ssum;  // (1/sum) * (1/sqrt(E))

    float4 acc = make_float4(0.f, 0.f, 0.f, 0.f);
#pragma unroll
    for (int j = 0; j < KW_; j++) {
        const float w = logits[j] * inv;
        acc.x += w * vreg[j].x;
        acc.y += w * vreg[j].y;
        acc.z += w * vreg[j].z;
        acc.w += w * vreg[j].w;
    }

    // coalesced float4 store; split_tile repacks for the out-projection GEMM
    float4* arow = (float4*)(g_attn + (((size_t)b * S_ + s) * H_ + h) * E_);
    arow[lane] = acc;
}

// ---------------------------------------------------------------------------
// Launch
// ---------------------------------------------------------------------------
extern "C" void kernel_launch(void* const* d_in, const int* in_sizes, int n_in,
                              void* d_out, int out_size)
{
    const float* x  = (const float*)d_in[0];
    const float* Wq = (const float*)d_in[1];
    const float* bq = (const float*)d_in[2];
    const float* Wk = (const float*)d_in[3];
    const float* bk = (const float*)d_in[4];
    const float* Wv = (const float*)d_in[5];
    const float* bv = (const float*)d_in[6];
    const float* Wo = (const float*)d_in[7];
    const float* bo = (const float*)d_in[8];
    const int*   dl = (const int*)d_in[9];
    float* out = (float*)d_out;

    // Not a stream op; graph-capture safe. Unconditional (no static guards).
    cudaFuncSetAttribute(gemm128_bf16, cudaFuncAttributeMaxDynamicSharedMemorySize, GEMM_SMEM);

    // prep: pack x into tile-ready hi/lo blocks; transpose+split weights
    split_tile<<<dim3(32, 32), 256>>>(0, x);
    transpose_w_kernel<<<dim3(D_ / 32, E_ / 32, 3 * H_), dim3(32, 8)>>>(Wq, Wk, Wv);
    transpose_wo_kernel<<<dim3(D_ / 32, D_ / 32), dim3(32, 8)>>>(Wo);

    // Q/K/V projections on tensor cores (bf16x3)
    gemm128_bf16<<<dim3(M_ / 128, H_, 3), 256, GEMM_SMEM>>>(0, bq, bk, bv, bo, out);

    // windowed attention (float output) + repack
    attn_kernel<<<(B_ * H_ * S_) / 8, 256>>>(bk, bv, dl);
    split_tile<<<dim3(32, 32), 256>>>(1, x);

    // out-projection on tensor cores (bf16x3)
    gemm128_bf16<<<dim3(M_ / 128, D_ / 128, 1), 256, GEMM_SMEM>>>(1, bq, bk, bv, bo, out);
}

// round 15
// speedup vs baseline: 3.0217x; 1.1847x over previous
#include <cuda_runtime.h>
#include <cuda_bf16.h>
#include <cstdint>

#define B_  2
#define S_  2048
#define D_  1024
#define H_  8
#define E_  128
#define KW_ 16
#define M_  (B_ * S_)        // 4096 rows

// Chunk layout: per (128-row tile, 32-k chunk): hi sub-block then lo sub-block.
// Element (row, k): kg = k>>3; 16B group at uint32 index
//   poff(row,kg) = row*16 + ((kg ^ ((row>>1)&3)) << 2)
// within a 2048-uint32 (8 KB) sub-block. Identity-copyable into smem stages.
#define SUB 2048                 // uint32 per sub-block (8 KB)
#define BLK 4096                 // uint32 per operand chunk block (hi+lo, 16 KB)
#define STG_BYTES 32768          // stage: Ah Al Bh Bl = 32 KB
#define GEMM_SMEM (3 * STG_BYTES)    // 96 KB; 2 CTAs/SM fits 228 KB

// ---------------------------------------------------------------------------
// Scratch (__device__ globals; allocation-free). Referenced ONLY from device
// code — never passed as kernel args from host (host shadow != dev addr).
// ---------------------------------------------------------------------------
__device__ float    g_q[4194304];        // [B,H,S,E]
__device__ float    g_k[4194304];
__device__ float    g_v[4194304];
__device__ float    g_attn[4194304];     // [B,S,H,E] float (attn output)
__device__ uint32_t g_x2[4194304];       // x:    [T=32][C=32] blocks
__device__ uint32_t g_w2[3145728];       // W^T:  [z=24][C=32] blocks
__device__ uint32_t g_wo2[1048576];      // Wo^T: [nt=8][C=32] blocks
__device__ uint32_t g_a2[4194304];       // attn: [T=32][C=32] blocks

// ---------------------------------------------------------------------------
// Helpers
// ---------------------------------------------------------------------------
__device__ __forceinline__ void split2(float a, float b, uint32_t& hi, uint32_t& lo) {
    __nv_bfloat16 ha = __float2bfloat16(a);
    __nv_bfloat16 hb = __float2bfloat16(b);
    __nv_bfloat16 la = __float2bfloat16(a - __bfloat162float(ha));
    __nv_bfloat16 lb = __float2bfloat16(b - __bfloat162float(hb));
    hi = ((uint32_t)__bfloat16_as_ushort(hb) << 16) | (uint32_t)__bfloat16_as_ushort(ha);
    lo = ((uint32_t)__bfloat16_as_ushort(lb) << 16) | (uint32_t)__bfloat16_as_ushort(la);
}

__device__ __forceinline__ void mma_bf16(float d[4], const uint32_t a[4],
                                         uint32_t b0, uint32_t b1) {
    asm volatile(
        "mma.sync.aligned.m16n8k16.row.col.f32.bf16.bf16.f32 "
        "{%0,%1,%2,%3}, {%4,%5,%6,%7}, {%8,%9}, {%0,%1,%2,%3};"
        : "+f"(d[0]), "+f"(d[1]), "+f"(d[2]), "+f"(d[3])
        : "r"(a[0]), "r"(a[1]), "r"(a[2]), "r"(a[3]), "r"(b0), "r"(b1));
}

__device__ __forceinline__ uint32_t smem_u32(const void* p) {
    uint32_t a;
    asm("{ .reg .u64 t; cvta.to.shared.u64 t, %1; cvt.u32.u64 %0, t; }" : "=r"(a) : "l"(p));
    return a;
}

#define CP16(dst, src) \
    asm volatile("cp.async.cg.shared.global [%0], [%1], 16;" :: "r"(dst), "l"(src))
#define CPCOMMIT() asm volatile("cp.async.commit_group;" ::: "memory")
#define CPWAIT1()  asm volatile("cp.async.wait_group 1;"  ::: "memory")

#define LDM4(r, a) \
    asm volatile("ldmatrix.sync.aligned.m8n8.x4.shared.b16 {%0,%1,%2,%3}, [%4];" \
        : "=r"((r)[0]), "=r"((r)[1]), "=r"((r)[2]), "=r"((r)[3]) : "r"(a))

__device__ __forceinline__ int poff(int row, int kg) {
    return row * 16 + ((kg ^ ((row >> 1) & 3)) << 2);
}

// ---------------------------------------------------------------------------
// split_tile: [4096 x 1024] fp32 row-major -> chunk blocks (hi/lo).
// which==0: x -> g_x2;  which==1: g_attn -> g_a2.
// grid (C=32, T=32), 256 threads. Coalesced reads AND writes (verified).
// ---------------------------------------------------------------------------
__global__ __launch_bounds__(256) void split_tile(int which,
                                                  const float* __restrict__ xsrc)
{
    const float* src = (which == 0) ? xsrc : g_attn;
    uint32_t*    dst = (which == 0) ? g_x2 : g_a2;

    __shared__ float s[128][33];
    const int C = blockIdx.x, T = blockIdx.y;
    const int tid = threadIdx.x;

#pragma unroll
    for (int it = 0; it < 4; it++) {
        const int v  = it * 256 + tid;
        const int r  = v >> 3;
        const int c4 = (v & 7) * 4;
        float4 x4 = *(const float4*)(src + (size_t)(T * 128 + r) * 1024 + C * 32 + c4);
        s[r][c4 + 0] = x4.x; s[r][c4 + 1] = x4.y;
        s[r][c4 + 2] = x4.z; s[r][c4 + 3] = x4.w;
    }
    __syncthreads();

    uint32_t* base = dst + (size_t)(T * 32 + C) * BLK;
#pragma unroll
    for (int it = 0; it < 2; it++) {
        const int task = it * 256 + tid;
        const int row = task >> 2, kg = task & 3;
        uint4 hi, lo;
        split2(s[row][kg * 8 + 0], s[row][kg * 8 + 1], hi.x, lo.x);
        split2(s[row][kg * 8 + 2], s[row][kg * 8 + 3], hi.y, lo.y);
        split2(s[row][kg * 8 + 4], s[row][kg * 8 + 5], hi.z, lo.z);
        split2(s[row][kg * 8 + 6], s[row][kg * 8 + 7], hi.w, lo.w);
        const int po = poff(row, kg);
        *(uint4*)(base + po)       = hi;
        *(uint4*)(base + SUB + po) = lo;
    }
}

// W^T blocks: z = sel*8 + h; rows = e (0..127), k = d. grid (32, 4, 24), (32,8).
__global__ void transpose_w_kernel(const float* __restrict__ Wq,
                                   const float* __restrict__ Wk,
                                   const float* __restrict__ Wv) {
    const int z = blockIdx.z;
    const float* W = ((z < 8) ? Wq : (z < 16) ? Wk : Wv) + (size_t)(z & 7) * D_ * E_;
    __shared__ float tt[32][33];
    const int d0 = blockIdx.x * 32, e0 = blockIdx.y * 32;
    const int tx = threadIdx.x, ty = threadIdx.y;
#pragma unroll
    for (int i = 0; i < 32; i += 8)
        tt[ty + i][tx] = W[(size_t)(d0 + ty + i) * E_ + e0 + tx];   // tt[d_local][e_local]
    __syncthreads();
    if (ty < 4) {
        const int kg = ty;
        const int e  = e0 + tx;          // row 0..127
        uint4 hi, lo;
        split2(tt[kg * 8 + 0][tx], tt[kg * 8 + 1][tx], hi.x, lo.x);
        split2(tt[kg * 8 + 2][tx], tt[kg * 8 + 3][tx], hi.y, lo.y);
        split2(tt[kg * 8 + 4][tx], tt[kg * 8 + 5][tx], hi.z, lo.z);
        split2(tt[kg * 8 + 6][tx], tt[kg * 8 + 7][tx], hi.w, lo.w);
        uint32_t* base = g_w2 + (size_t)(z * 32 + (d0 >> 5)) * BLK;
        const int po = poff(e, kg);
        *(uint4*)(base + po)       = hi;
        *(uint4*)(base + SUB + po) = lo;
    }
}

// Wo^T blocks: rows = n (0..1023 -> nt,nloc), k = h*E+e. grid (32, 32), (32,8).
__global__ void transpose_wo_kernel(const float* __restrict__ Wo) {
    __shared__ float tt[32][33];
    const int k0 = blockIdx.x * 32, n0 = blockIdx.y * 32;
    const int tx = threadIdx.x, ty = threadIdx.y;
#pragma unroll
    for (int i = 0; i < 32; i += 8)
        tt[ty + i][tx] = Wo[(size_t)(k0 + ty + i) * D_ + n0 + tx];  // tt[k_local][n_local]
    __syncthreads();
    if (ty < 4) {
        const int kg   = ty;
        const int nt   = n0 >> 7;
        const int nloc = (n0 & 96) + tx;
        uint4 hi, lo;
        split2(tt[kg * 8 + 0][tx], tt[kg * 8 + 1][tx], hi.x, lo.x);
        split2(tt[kg * 8 + 2][tx], tt[kg * 8 + 3][tx], hi.y, lo.y);
        split2(tt[kg * 8 + 4][tx], tt[kg * 8 + 5][tx], hi.z, lo.z);
        split2(tt[kg * 8 + 6][tx], tt[kg * 8 + 7][tx], hi.w, lo.w);
        uint32_t* base = g_wo2 + (size_t)(nt * 32 + (k0 >> 5)) * BLK;
        const int po = poff(nloc, kg);
        *(uint4*)(base + po)       = hi;
        *(uint4*)(base + SUB + po) = lo;
    }
}

// ---------------------------------------------------------------------------
// bf16x3 mma.sync GEMM: ldmatrix fragments + cp.async 3-stage pipeline.
//   D[128,128] = A[128,1024] * Bt[128,1024]^T (+bias)
//   acc += Ah*Bh + Ah*Bl + Al*Bh   (fp32 accumulate)
// Stage (32 KB): Ah @0, Al @8192, Bh @16384, Bl @24576 (bytes).
// mode 0: Q/K/V (grid 32 x 8 x 3); mode 1: out-proj (grid 32 x 8)
// ---------------------------------------------------------------------------
__global__ __launch_bounds__(256, 2) void gemm128_bf16(
    int mode,
    const float* __restrict__ bq, const float* __restrict__ bk,
    const float* __restrict__ bv, const float* __restrict__ bo,
    float* __restrict__ oout)
{
    extern __shared__ uint32_t dyn[];
    const uint32_t sb = smem_u32(dyn);

    const int tid  = threadIdx.x;
    const int wid  = tid >> 5;
    const int lane = tid & 31;
    const int g    = lane >> 2;      // epilogue row group
    const int t    = lane & 3;       // epilogue col pair
    const int m0   = blockIdx.x * 128;
    const int mb   = (wid & 1) * 64;     // warp m-offset
    const int nb   = (wid >> 1) * 32;    // warp n-offset

    const uint32_t *Asrc, *Bsrc;
    const float* bias;
    if (mode == 0) {
        const int h = blockIdx.y, sel = blockIdx.z;
        Asrc = g_x2 + (size_t)blockIdx.x * 32 * BLK;
        Bsrc = g_w2 + (size_t)(sel * H_ + h) * 32 * BLK;
        bias = ((sel == 0) ? bq : (sel == 1) ? bk : bv) + h * E_;
    } else {
        Asrc = g_a2  + (size_t)blockIdx.x * 32 * BLK;
        Bsrc = g_wo2 + (size_t)blockIdx.y * 32 * BLK;
        bias = bo + blockIdx.y * 128;
    }

    float acc[4][4][4];
#pragma unroll
    for (int i = 0; i < 4; i++)
#pragma unroll
        for (int j = 0; j < 4; j++)
#pragma unroll
            for (int r = 0; r < 4; r++) acc[i][j][r] = 0.f;

    // ldmatrix per-lane bases (standard m16n8k16 fragment <-> x4 matrices)
    const int arow  = mb + (lane & 7) + ((lane >> 3) & 1) * 8;   // + mt*16
    const int akbit = lane >> 4;                                  // k-half
    const int brow  = nb + (lane & 7) + ((lane >> 4) & 1) * 8;   // + p*16
    const int bkbit = (lane >> 3) & 1;

    // identity cp.async: chunk block c -> stage st (A 16 KB then B 16 KB)
    auto issue = [&](int c, int st) {
        const uint32_t dA = sb + st * STG_BYTES;
        const char* sA = (const char*)(Asrc + (size_t)c * BLK);
        const char* sB = (const char*)(Bsrc + (size_t)c * BLK);
#pragma unroll
        for (int j = 0; j < 4; j++) {
            const int v = j * 256 + tid;
            CP16(dA + v * 16,         sA + v * 16);
            CP16(dA + 16384 + v * 16, sB + v * 16);
        }
    };

    issue(0, 0); CPCOMMIT();
    issue(1, 1); CPCOMMIT();

    for (int i = 0; i < 32; i++) {
        CPWAIT1();            // chunk i resident
        __syncthreads();      // publish; prior stage reads complete
        if (i + 2 < 32) issue(i + 2, (i + 2) % 3);
        CPCOMMIT();           // always commit to keep group accounting

        const uint32_t stg = sb + (i % 3) * STG_BYTES;

#pragma unroll
        for (int kk = 0; kk < 2; kk++) {
            uint32_t ah[4][4], al[4][4];
#pragma unroll
            for (int mt = 0; mt < 4; mt++) {
                const int row = arow + mt * 16;
                const uint32_t off = row * 64 + (((2 * kk + akbit) ^ ((row >> 1) & 3)) << 4);
                LDM4(ah[mt], stg + off);
                LDM4(al[mt], stg + 8192 + off);
            }
            uint32_t bh[2][4], bl[2][4];
#pragma unroll
            for (int p = 0; p < 2; p++) {
                const int row = brow + p * 16;
                const uint32_t off = row * 64 + (((2 * kk + bkbit) ^ ((row >> 1) & 3)) << 4);
                LDM4(bh[p], stg + 16384 + off);
                LDM4(bl[p], stg + 24576 + off);
            }
#pragma unroll
            for (int nt = 0; nt < 4; nt++) {
                const uint32_t bh0 = bh[nt >> 1][(nt & 1) * 2];
                const uint32_t bh1 = bh[nt >> 1][(nt & 1) * 2 + 1];
                const uint32_t bl0 = bl[nt >> 1][(nt & 1) * 2];
                const uint32_t bl1 = bl[nt >> 1][(nt & 1) * 2 + 1];
#pragma unroll
                for (int mt = 0; mt < 4; mt++) {
                    mma_bf16(acc[mt][nt], ah[mt], bh0, bh1);
                    mma_bf16(acc[mt][nt], ah[mt], bl0, bl1);
                    mma_bf16(acc[mt][nt], al[mt], bh0, bh1);
                }
            }
        }
    }

    // epilogue: row = mb+mt*16+g (+8), col = nb+nt*8+2t (+1)
    const int h = blockIdx.y, sel = blockIdx.z;
#pragma unroll
    for (int mt = 0; mt < 4; mt++) {
        const int m_lo = m0 + mb + mt * 16 + g;
#pragma unroll
        for (int rh = 0; rh < 2; rh++) {
            const int m = m_lo + rh * 8;
            float* dst;
            if (mode == 0) {
                const int bb = m >> 11;
                const int s  = m & (S_ - 1);
                float* out = (sel == 0) ? g_q : (sel == 1) ? g_k : g_v;
                dst = out + (((size_t)bb * H_ + h) * S_ + s) * E_;
            } else {
                dst = oout + (size_t)m * D_ + blockIdx.y * 128;
            }
#pragma unroll
            for (int nt = 0; nt < 4; nt++) {
                const int cn = nb + nt * 8 + 2 * t;
                float2 v;
                v.x = acc[mt][nt][2 * rh + 0] + bias[cn];
                v.y = acc[mt][nt][2 * rh + 1] + bias[cn + 1];
                *(float2*)(dst + cn) = v;
            }
        }
    }
}

// ---------------------------------------------------------------------------
// Windowed attention: one warp per (b, h, s) query.
// Output: plain float [B,S,H,E] (coalesced); repacked by split_tile after.
// ---------------------------------------------------------------------------
__global__ __launch_bounds__(256) void attn_kernel(
    const float* __restrict__ bk,
    const float* __restrict__ bv,
    const int*   __restrict__ dilations)
{
    const int warp = (blockIdx.x * blockDim.x + threadIdx.x) >> 5;
    const int lane = threadIdx.x & 31;
    const int s = warp & (S_ - 1);
    const int h = (warp >> 11) & (H_ - 1);
    const int b = warp >> 14;

    const int d = dilations[h];
    const int center = (d * (KW_ - 1)) >> 1;

    const size_t head_base = ((size_t)b * H_ + h) * S_ * E_;
    const float4 q4 = ((const float4*)(g_q + head_base + (size_t)s * E_))[lane];
    const float4* kbase = (const float4*)(g_k + head_base);
    const float4* vbase = (const float4*)(g_v + head_base);
    const float4 bk4 = ((const float4*)(bk + h * E_))[lane];
    const float4 bv4 = ((const float4*)(bv + h * E_))[lane];

    float logits[KW_];
    float4 vreg[KW_];

#pragma unroll
    for (int j = 0; j < KW_; j++) {
        const int pos = s + d * j - center;
        const bool ok = (pos >= 0) && (pos < S_);
        float4 k4;
        if (ok) {
            k4      = kbase[(size_t)pos * 32 + lane];
            vreg[j] = vbase[(size_t)pos * 32 + lane];
        } else {
            k4      = bk4;
            vreg[j] = bv4;
        }
        float p = k4.x * q4.x + k4.y * q4.y + k4.z * q4.z + k4.w * q4.w;
#pragma unroll
        for (int o = 16; o > 0; o >>= 1)
            p += __shfl_xor_sync(0xffffffffu, p, o);
        logits[j] = p;
    }

    float mx = logits[0];
#pragma unroll
    for (int j = 1; j < KW_; j++) mx = fmaxf(mx, logits[j]);
    float ssum = 0.f;
#pragma unroll
    for (int j = 0; j < KW_; j++) {
        logits[j] = __expf(logits[j] - mx);
        ssum += logits[j];
    }
    const float inv = 0.08838834764831845f / ssum;  // (1/sum) * (1/sqrt(E))

    float4 acc = make_float4(0.f, 0.f, 0.f, 0.f);
#pragma unroll
    for (int j = 0; j < KW_; j++) {
        const float w = logits[j] * inv;
        acc.x += w * vreg[j].x;
        acc.y += w * vreg[j].y;
        acc.z += w * vreg[j].z;
        acc.w += w * vreg[j].w;
    }

    float4* arow = (float4*)(g_attn + (((size_t)b * S_ + s) * H_ + h) * E_);
    arow[lane] = acc;
}

// ---------------------------------------------------------------------------
// Launch
// ---------------------------------------------------------------------------
extern "C" void kernel_launch(void* const* d_in, const int* in_sizes, int n_in,
                              void* d_out, int out_size)
{
    const float* x  = (const float*)d_in[0];
    const float* Wq = (const float*)d_in[1];
    const float* bq = (const float*)d_in[2];
    const float* Wk = (const float*)d_in[3];
    const float* bk = (const float*)d_in[4];
    const float* Wv = (const float*)d_in[5];
    const float* bv = (const float*)d_in[6];
    const float* Wo = (const float*)d_in[7];
    const float* bo = (const float*)d_in[8];
    const int*   dl = (const int*)d_in[9];
    float* out = (float*)d_out;

    // Not a stream op; graph-capture safe. Unconditional (no static guards).
    cudaFuncSetAttribute(gemm128_bf16, cudaFuncAttributeMaxDynamicSharedMemorySize, GEMM_SMEM);

    // prep: pack operands into chunk blocks
    split_tile<<<dim3(32, 32), 256>>>(0, x);
    transpose_w_kernel<<<dim3(32, 4, 24), dim3(32, 8)>>>(Wq, Wk, Wv);
    transpose_wo_kernel<<<dim3(32, 32), 256 / 8 == 32 ? dim3(32, 8) : dim3(32, 8)>>>(Wo);

    // Q/K/V projections on tensor cores (bf16x3, ldmatrix path)
    gemm128_bf16<<<dim3(M_ / 128, H_, 3), 256, GEMM_SMEM>>>(0, bq, bk, bv, bo, out);

    // windowed attention (float output) + repack
    attn_kernel<<<(B_ * H_ * S_) / 8, 256>>>(bk, bv, dl);
    split_tile<<<dim3(32, 32), 256>>>(1, x);

    // out-projection on tensor cores (bf16x3)
    gemm128_bf16<<<dim3(M_ / 128, D_ / 128, 1), 256, GEMM_SMEM>>>(1, bq, bk, bv, bo, out);
}

// round 16
// speedup vs baseline: 3.1669x; 1.0480x over previous
#include <cuda_runtime.h>
#include <cuda_bf16.h>
#include <cstdint>

#define B_  2
#define S_  2048
#define D_  1024
#define H_  8
#define E_  128
#define KW_ 16
#define M_  (B_ * S_)        // 4096 rows

// Chunk layout: per (128-row tile, 32-k chunk): hi sub-block then lo sub-block.
// Element (row, k): kg = k>>3; 16B group at uint32 index
//   poff(row,kg) = row*16 + ((kg ^ ((row>>1)&3)) << 2)
#define SUB 2048                 // uint32 per sub-block (8 KB)
#define BLK 4096                 // uint32 per operand chunk block (hi+lo, 16 KB)
#define STG_BYTES 32768          // stage: Ah Al Bh Bl = 32 KB
#define GEMM_SMEM (3 * STG_BYTES)    // 96 KB; 2 CTAs/SM fits 228 KB

// ---------------------------------------------------------------------------
// Scratch (__device__ globals; allocation-free). Referenced ONLY from device
// code — never passed as kernel args from host (host shadow != dev addr).
// ---------------------------------------------------------------------------
__device__ float    g_q[4194304];        // [B,H,S,E]
__device__ float    g_k[4194304];
__device__ float    g_v[4194304];
__device__ uint32_t g_x2[4194304];       // x:    [T=32][C=32] blocks
__device__ uint32_t g_w2[3145728];       // W^T:  [z=24][C=32] blocks
__device__ uint32_t g_wo2[1048576];      // Wo^T: [nt=8][C=32] blocks
__device__ uint32_t g_a2[4194304];       // attn: [T=32][C=32] blocks

// ---------------------------------------------------------------------------
// Helpers
// ---------------------------------------------------------------------------
__device__ __forceinline__ void split2(float a, float b, uint32_t& hi, uint32_t& lo) {
    __nv_bfloat16 ha = __float2bfloat16(a);
    __nv_bfloat16 hb = __float2bfloat16(b);
    __nv_bfloat16 la = __float2bfloat16(a - __bfloat162float(ha));
    __nv_bfloat16 lb = __float2bfloat16(b - __bfloat162float(hb));
    hi = ((uint32_t)__bfloat16_as_ushort(hb) << 16) | (uint32_t)__bfloat16_as_ushort(ha);
    lo = ((uint32_t)__bfloat16_as_ushort(lb) << 16) | (uint32_t)__bfloat16_as_ushort(la);
}

__device__ __forceinline__ void mma_bf16(float d[4], const uint32_t a[4],
                                         uint32_t b0, uint32_t b1) {
    asm volatile(
        "mma.sync.aligned.m16n8k16.row.col.f32.bf16.bf16.f32 "
        "{%0,%1,%2,%3}, {%4,%5,%6,%7}, {%8,%9}, {%0,%1,%2,%3};"
        : "+f"(d[0]), "+f"(d[1]), "+f"(d[2]), "+f"(d[3])
        : "r"(a[0]), "r"(a[1]), "r"(a[2]), "r"(a[3]), "r"(b0), "r"(b1));
}

__device__ __forceinline__ uint32_t smem_u32(const void* p) {
    uint32_t a;
    asm("{ .reg .u64 t; cvta.to.shared.u64 t, %1; cvt.u32.u64 %0, t; }" : "=r"(a) : "l"(p));
    return a;
}

#define CP16(dst, src) \
    asm volatile("cp.async.cg.shared.global [%0], [%1], 16;" :: "r"(dst), "l"(src))
#define CPCOMMIT() asm volatile("cp.async.commit_group;" ::: "memory")
#define CPWAIT1()  asm volatile("cp.async.wait_group 1;"  ::: "memory")

#define LDM4(r, a) \
    asm volatile("ldmatrix.sync.aligned.m8n8.x4.shared.b16 {%0,%1,%2,%3}, [%4];" \
        : "=r"((r)[0]), "=r"((r)[1]), "=r"((r)[2]), "=r"((r)[3]) : "r"(a))

__device__ __forceinline__ int poff(int row, int kg) {
    return row * 16 + ((kg ^ ((row >> 1) & 3)) << 2);
}

// ---------------------------------------------------------------------------
// split_tile: x [4096 x 1024] fp32 row-major -> g_x2 chunk blocks (hi/lo).
// grid (C=32, T=32), 256 threads. Coalesced reads AND writes.
// ---------------------------------------------------------------------------
__global__ __launch_bounds__(256) void split_tile(const float* __restrict__ src)
{
    __shared__ float s[128][33];
    const int C = blockIdx.x, T = blockIdx.y;
    const int tid = threadIdx.x;

#pragma unroll
    for (int it = 0; it < 4; it++) {
        const int v  = it * 256 + tid;
        const int r  = v >> 3;
        const int c4 = (v & 7) * 4;
        float4 x4 = *(const float4*)(src + (size_t)(T * 128 + r) * 1024 + C * 32 + c4);
        s[r][c4 + 0] = x4.x; s[r][c4 + 1] = x4.y;
        s[r][c4 + 2] = x4.z; s[r][c4 + 3] = x4.w;
    }
    __syncthreads();

    uint32_t* base = g_x2 + (size_t)(T * 32 + C) * BLK;
#pragma unroll
    for (int it = 0; it < 2; it++) {
        const int task = it * 256 + tid;
        const int row = task >> 2, kg = task & 3;
        uint4 hi, lo;
        split2(s[row][kg * 8 + 0], s[row][kg * 8 + 1], hi.x, lo.x);
        split2(s[row][kg * 8 + 2], s[row][kg * 8 + 3], hi.y, lo.y);
        split2(s[row][kg * 8 + 4], s[row][kg * 8 + 5], hi.z, lo.z);
        split2(s[row][kg * 8 + 6], s[row][kg * 8 + 7], hi.w, lo.w);
        const int po = poff(row, kg);
        *(uint4*)(base + po)       = hi;
        *(uint4*)(base + SUB + po) = lo;
    }
}

// W^T blocks: z = sel*8 + h; rows = e (0..127), k = d. grid (32, 4, 24), (32,8).
__global__ void transpose_w_kernel(const float* __restrict__ Wq,
                                   const float* __restrict__ Wk,
                                   const float* __restrict__ Wv) {
    const int z = blockIdx.z;
    const float* W = ((z < 8) ? Wq : (z < 16) ? Wk : Wv) + (size_t)(z & 7) * D_ * E_;
    __shared__ float tt[32][33];
    const int d0 = blockIdx.x * 32, e0 = blockIdx.y * 32;
    const int tx = threadIdx.x, ty = threadIdx.y;
#pragma unroll
    for (int i = 0; i < 32; i += 8)
        tt[ty + i][tx] = W[(size_t)(d0 + ty + i) * E_ + e0 + tx];   // tt[d_local][e_local]
    __syncthreads();
    if (ty < 4) {
        const int kg = ty;
        const int e  = e0 + tx;          // row 0..127
        uint4 hi, lo;
        split2(tt[kg * 8 + 0][tx], tt[kg * 8 + 1][tx], hi.x, lo.x);
        split2(tt[kg * 8 + 2][tx], tt[kg * 8 + 3][tx], hi.y, lo.y);
        split2(tt[kg * 8 + 4][tx], tt[kg * 8 + 5][tx], hi.z, lo.z);
        split2(tt[kg * 8 + 6][tx], tt[kg * 8 + 7][tx], hi.w, lo.w);
        uint32_t* base = g_w2 + (size_t)(z * 32 + (d0 >> 5)) * BLK;
        const int po = poff(e, kg);
        *(uint4*)(base + po)       = hi;
        *(uint4*)(base + SUB + po) = lo;
    }
}

// Wo^T blocks: rows = n (0..1023 -> nt,nloc), k = h*E+e. grid (32, 32), (32,8).
__global__ void transpose_wo_kernel(const float* __restrict__ Wo) {
    __shared__ float tt[32][33];
    const int k0 = blockIdx.x * 32, n0 = blockIdx.y * 32;
    const int tx = threadIdx.x, ty = threadIdx.y;
#pragma unroll
    for (int i = 0; i < 32; i += 8)
        tt[ty + i][tx] = Wo[(size_t)(k0 + ty + i) * D_ + n0 + tx];  // tt[k_local][n_local]
    __syncthreads();
    if (ty < 4) {
        const int kg   = ty;
        const int nt   = n0 >> 7;
        const int nloc = (n0 & 96) + tx;
        uint4 hi, lo;
        split2(tt[kg * 8 + 0][tx], tt[kg * 8 + 1][tx], hi.x, lo.x);
        split2(tt[kg * 8 + 2][tx], tt[kg * 8 + 3][tx], hi.y, lo.y);
        split2(tt[kg * 8 + 4][tx], tt[kg * 8 + 5][tx], hi.z, lo.z);
        split2(tt[kg * 8 + 6][tx], tt[kg * 8 + 7][tx], hi.w, lo.w);
        uint32_t* base = g_wo2 + (size_t)(nt * 32 + (k0 >> 5)) * BLK;
        const int po = poff(nloc, kg);
        *(uint4*)(base + po)       = hi;
        *(uint4*)(base + SUB + po) = lo;
    }
}

// ---------------------------------------------------------------------------
// bf16x3 mma.sync GEMM: ldmatrix fragments + cp.async 3-stage pipeline.
//   acc += Ah*Bh ; acc += Ah*Bl ; acc += Al*Bh   (pass-major ordering)
// Stage (32 KB): Ah @0, Al @8192, Bh @16384, Bl @24576 (bytes).
// mode 0: Q/K/V (grid 32 x 8 x 3); mode 1: out-proj (grid 32 x 8)
// ---------------------------------------------------------------------------
__global__ __launch_bounds__(256, 2) void gemm128_bf16(
    int mode,
    const float* __restrict__ bq, const float* __restrict__ bk,
    const float* __restrict__ bv, const float* __restrict__ bo,
    float* __restrict__ oout)
{
    extern __shared__ uint32_t dyn[];
    const uint32_t sb = smem_u32(dyn);

    const int tid  = threadIdx.x;
    const int wid  = tid >> 5;
    const int lane = tid & 31;
    const int g    = lane >> 2;      // epilogue row group
    const int t    = lane & 3;       // epilogue col pair
    const int m0   = blockIdx.x * 128;
    const int mb   = (wid & 1) * 64;     // warp m-offset
    const int nb   = (wid >> 1) * 32;    // warp n-offset

    const uint32_t *Asrc, *Bsrc;
    const float* bias;
    if (mode == 0) {
        const int h = blockIdx.y, sel = blockIdx.z;
        Asrc = g_x2 + (size_t)blockIdx.x * 32 * BLK;
        Bsrc = g_w2 + (size_t)(sel * H_ + h) * 32 * BLK;
        bias = ((sel == 0) ? bq : (sel == 1) ? bk : bv) + h * E_;
    } else {
        Asrc = g_a2  + (size_t)blockIdx.x * 32 * BLK;
        Bsrc = g_wo2 + (size_t)blockIdx.y * 32 * BLK;
        bias = bo + blockIdx.y * 128;
    }

    float acc[4][4][4];
#pragma unroll
    for (int i = 0; i < 4; i++)
#pragma unroll
        for (int j = 0; j < 4; j++)
#pragma unroll
            for (int r = 0; r < 4; r++) acc[i][j][r] = 0.f;

    // ldmatrix per-lane bases (standard m16n8k16 fragment <-> x4 matrices)
    const int arow  = mb + (lane & 7) + ((lane >> 3) & 1) * 8;   // + mt*16
    const int akbit = lane >> 4;                                  // k-half
    const int brow  = nb + (lane & 7) + ((lane >> 4) & 1) * 8;   // + p*16
    const int bkbit = (lane >> 3) & 1;

    // identity cp.async: chunk block c -> stage st (A 16 KB then B 16 KB)
    auto issue = [&](int c, int st) {
        const uint32_t dA = sb + st * STG_BYTES;
        const char* sA = (const char*)(Asrc + (size_t)c * BLK);
        const char* sB = (const char*)(Bsrc + (size_t)c * BLK);
#pragma unroll
        for (int j = 0; j < 4; j++) {
            const int v = j * 256 + tid;
            CP16(dA + v * 16,         sA + v * 16);
            CP16(dA + 16384 + v * 16, sB + v * 16);
        }
    };

    issue(0, 0); CPCOMMIT();
    issue(1, 1); CPCOMMIT();

    for (int i = 0; i < 32; i++) {
        CPWAIT1();            // chunk i resident
        __syncthreads();      // publish; prior stage reads complete
        if (i + 2 < 32) issue(i + 2, (i + 2) % 3);
        CPCOMMIT();           // always commit to keep group accounting

        const uint32_t stg = sb + (i % 3) * STG_BYTES;

#pragma unroll
        for (int kk = 0; kk < 2; kk++) {
            uint32_t ah[4][4], al[4][4];
#pragma unroll
            for (int mt = 0; mt < 4; mt++) {
                const int row = arow + mt * 16;
                const uint32_t off = row * 64 + (((2 * kk + akbit) ^ ((row >> 1) & 3)) << 4);
                LDM4(ah[mt], stg + off);
                LDM4(al[mt], stg + 8192 + off);
            }
            uint32_t bh[2][4], bl[2][4];
#pragma unroll
            for (int p = 0; p < 2; p++) {
                const int row = brow + p * 16;
                const uint32_t off = row * 64 + (((2 * kk + bkbit) ^ ((row >> 1) & 3)) << 4);
                LDM4(bh[p], stg + 16384 + off);
                LDM4(bl[p], stg + 24576 + off);
            }
            // pass-major: break same-accumulator RAW chains
#pragma unroll
            for (int nt = 0; nt < 4; nt++) {
                const uint32_t b0 = bh[nt >> 1][(nt & 1) * 2];
                const uint32_t b1 = bh[nt >> 1][(nt & 1) * 2 + 1];
#pragma unroll
                for (int mt = 0; mt < 4; mt++)
                    mma_bf16(acc[mt][nt], ah[mt], b0, b1);
            }
#pragma unroll
            for (int nt = 0; nt < 4; nt++) {
                const uint32_t b0 = bl[nt >> 1][(nt & 1) * 2];
                const uint32_t b1 = bl[nt >> 1][(nt & 1) * 2 + 1];
#pragma unroll
                for (int mt = 0; mt < 4; mt++)
                    mma_bf16(acc[mt][nt], ah[mt], b0, b1);
            }
#pragma unroll
            for (int nt = 0; nt < 4; nt++) {
                const uint32_t b0 = bh[nt >> 1][(nt & 1) * 2];
                const uint32_t b1 = bh[nt >> 1][(nt & 1) * 2 + 1];
#pragma unroll
                for (int mt = 0; mt < 4; mt++)
                    mma_bf16(acc[mt][nt], al[mt], b0, b1);
            }
        }
    }

    // epilogue: row = mb+mt*16+g (+8), col = nb+nt*8+2t (+1)
    const int h = blockIdx.y, sel = blockIdx.z;
#pragma unroll
    for (int mt = 0; mt < 4; mt++) {
        const int m_lo = m0 + mb + mt * 16 + g;
#pragma unroll
        for (int rh = 0; rh < 2; rh++) {
            const int m = m_lo + rh * 8;
            float* dst;
            if (mode == 0) {
                const int bb = m >> 11;
                const int s  = m & (S_ - 1);
                float* out = (sel == 0) ? g_q : (sel == 1) ? g_k : g_v;
                dst = out + (((size_t)bb * H_ + h) * S_ + s) * E_;
            } else {
                dst = oout + (size_t)m * D_ + blockIdx.y * 128;
            }
#pragma unroll
            for (int nt = 0; nt < 4; nt++) {
                const int cn = nb + nt * 8 + 2 * t;
                float2 v;
                v.x = acc[mt][nt][2 * rh + 0] + bias[cn];
                v.y = acc[mt][nt][2 * rh + 1] + bias[cn + 1];
                *(float2*)(dst + cn) = v;
            }
        }
    }
}

// ---------------------------------------------------------------------------
// Windowed attention: 8 lanes per query, 4 queries per warp, two-phase.
// Lane owns interleaved 16-float slice: floats {i*32 + sl*4 .. +3}, i=0..3
// (per-instruction coalesced 128B row segments). 3-level shfl reduce (width 8).
// Output packed DIRECTLY into g_a2 chunk blocks (no intermediate tensor).
// ---------------------------------------------------------------------------
__global__ __launch_bounds__(256) void attn_kernel(
    const float* __restrict__ bk,
    const float* __restrict__ bv,
    const int*   __restrict__ dilations)
{
    const int gw   = (blockIdx.x * blockDim.x + threadIdx.x) >> 5;  // 0..8191
    const int lane = threadIdx.x & 31;
    const int qi   = lane >> 3;      // query within warp
    const int sl   = lane & 7;       // sub-lane within query
    const int gq   = gw * 4 + qi;    // global query id
    const int s = gq & (S_ - 1);
    const int h = (gq >> 11) & (H_ - 1);
    const int b = gq >> 14;

    const int d = dilations[h];
    const int center = (d * (KW_ - 1)) >> 1;
    const size_t head_base = ((size_t)b * H_ + h) * S_ * E_;
    const int eo = sl * 4;           // float offset within each 32-float band

    float4 q[4], bkr[4];
#pragma unroll
    for (int i = 0; i < 4; i++) {
        q[i]   = *(const float4*)(g_q + head_base + (size_t)s * E_ + i * 32 + eo);
        bkr[i] = *(const float4*)(bk + h * E_ + i * 32 + eo);
    }

    // phase 1: logits
    float logits[KW_];
#pragma unroll
    for (int j = 0; j < KW_; j++) {
        const int pos = s + d * j - center;
        const bool ok = (pos >= 0) && (pos < S_);
        const float* kr = g_k + head_base + (size_t)(ok ? pos : 0) * E_;
        float p = 0.f;
#pragma unroll
        for (int i = 0; i < 4; i++) {
            float4 k4 = ok ? *(const float4*)(kr + i * 32 + eo) : bkr[i];
            p += k4.x * q[i].x + k4.y * q[i].y + k4.z * q[i].z + k4.w * q[i].w;
        }
        p += __shfl_xor_sync(0xffffffffu, p, 1, 8);
        p += __shfl_xor_sync(0xffffffffu, p, 2, 8);
        p += __shfl_xor_sync(0xffffffffu, p, 4, 8);
        logits[j] = p;
    }

    // softmax over KW (identical across the 8 lanes of a query)
    float mx = logits[0];
#pragma unroll
    for (int j = 1; j < KW_; j++) mx = fmaxf(mx, logits[j]);
    float ssum = 0.f;
#pragma unroll
    for (int j = 0; j < KW_; j++) {
        logits[j] = __expf(logits[j] - mx);
        ssum += logits[j];
    }
    const float inv = 0.08838834764831845f / ssum;  // (1/sum) * (1/sqrt(E))

    // phase 2: weighted V accumulation (V gathered once, never stored)
    float4 acc[4];
#pragma unroll
    for (int i = 0; i < 4; i++) acc[i] = make_float4(0.f, 0.f, 0.f, 0.f);
    float4 bvr[4];
#pragma unroll
    for (int i = 0; i < 4; i++)
        bvr[i] = *(const float4*)(bv + h * E_ + i * 32 + eo);

#pragma unroll
    for (int j = 0; j < KW_; j++) {
        const int pos = s + d * j - center;
        const bool ok = (pos >= 0) && (pos < S_);
        const float* vr = g_v + head_base + (size_t)(ok ? pos : 0) * E_;
        const float w = logits[j] * inv;
#pragma unroll
        for (int i = 0; i < 4; i++) {
            float4 v4 = ok ? *(const float4*)(vr + i * 32 + eo) : bvr[i];
            acc[i].x += w * v4.x; acc[i].y += w * v4.y;
            acc[i].z += w * v4.z; acc[i].w += w * v4.w;
        }
    }

    // pack directly into g_a2: float4 i covers k = h*128 + i*32 + sl*4 .. +3
    // -> chunk C = h*4+i, kg = sl>>1, pair offset (sl&1)*2
    const int m    = b * S_ + s;
    const int T    = m >> 7, mloc = m & 127;
    const int kg   = sl >> 1;
    const int sub2 = (sl & 1) * 2;
    const int po   = poff(mloc, kg) + sub2;
#pragma unroll
    for (int i = 0; i < 4; i++) {
        uint32_t h0, l0, h1, l1;
        split2(acc[i].x, acc[i].y, h0, l0);
        split2(acc[i].z, acc[i].w, h1, l1);
        uint32_t* base = g_a2 + (size_t)(T * 32 + h * 4 + i) * BLK;
        base[po]           = h0;
        base[po + 1]       = h1;
        base[SUB + po]     = l0;
        base[SUB + po + 1] = l1;
    }
}

// ---------------------------------------------------------------------------
// Launch
// ---------------------------------------------------------------------------
extern "C" void kernel_launch(void* const* d_in, const int* in_sizes, int n_in,
                              void* d_out, int out_size)
{
    const float* x  = (const float*)d_in[0];
    const float* Wq = (const float*)d_in[1];
    const float* bq = (const float*)d_in[2];
    const float* Wk = (const float*)d_in[3];
    const float* bk = (const float*)d_in[4];
    const float* Wv = (const float*)d_in[5];
    const float* bv = (const float*)d_in[6];
    const float* Wo = (const float*)d_in[7];
    const float* bo = (const float*)d_in[8];
    const int*   dl = (const int*)d_in[9];
    float* out = (float*)d_out;

    // Not a stream op; graph-capture safe. Unconditional (no static guards).
    cudaFuncSetAttribute(gemm128_bf16, cudaFuncAttributeMaxDynamicSharedMemorySize, GEMM_SMEM);

    // prep: pack operands into chunk blocks
    split_tile<<<dim3(32, 32), 256>>>(x);
    transpose_w_kernel<<<dim3(32, 4, 24), dim3(32, 8)>>>(Wq, Wk, Wv);
    transpose_wo_kernel<<<dim3(32, 32), dim3(32, 8)>>>(Wo);

    // Q/K/V projections on tensor cores (bf16x3, ldmatrix path)
    gemm128_bf16<<<dim3(M_ / 128, H_, 3), 256, GEMM_SMEM>>>(0, bq, bk, bv, bo, out);

    // windowed attention, packs g_a2 directly (8192 warps / 8 per block)
    attn_kernel<<<1024, 256>>>(bk, bv, dl);

    // out-projection on tensor cores (bf16x3)
    gemm128_bf16<<<dim3(M_ / 128, D_ / 128, 1), 256, GEMM_SMEM>>>(1, bq, bk, bv, bo, out);
}

// round 17
// speedup vs baseline: 3.1710x; 1.0013x over previous
#include <cuda_runtime.h>
#include <cuda_bf16.h>
#include <cstdint>

#define B_  2
#define S_  2048
#define D_  1024
#define H_  8
#define E_  128
#define KW_ 16
#define M_  (B_ * S_)        // 4096 rows

// Chunk layout: per (128-row tile, 32-k chunk): hi sub-block then lo sub-block.
// Element (row, k): kg = k>>3; 16B group at uint32 index
//   poff(row,kg) = row*16 + ((kg ^ ((row>>1)&3)) << 2)
#define SUB 2048                 // uint32 per sub-block (8 KB)
#define BLK 4096                 // uint32 per operand chunk block (hi+lo, 16 KB)
#define STG_BYTES 32768          // stage: Ah Al Bh Bl = 32 KB
#define GEMM_SMEM (3 * STG_BYTES)    // 96 KB; 2 CTAs/SM fits 228 KB

// ---------------------------------------------------------------------------
// Scratch (__device__ globals; allocation-free). Referenced ONLY from device
// code — never passed as kernel args from host (host shadow != dev addr).
// ---------------------------------------------------------------------------
__device__ float    g_q[4194304];        // [B,H,S,E]
__device__ float    g_k[4194304];
__device__ float    g_v[4194304];
__device__ uint32_t g_x2[4194304];       // x:    [T=32][C=32] blocks
__device__ uint32_t g_w2[3145728];       // W^T:  [z=24][C=32] blocks
__device__ uint32_t g_wo2[1048576];      // Wo^T: [nt=8][C=32] blocks
__device__ uint32_t g_a2[4194304];       // attn: [T=32][C=32] blocks

// ---------------------------------------------------------------------------
// Helpers
// ---------------------------------------------------------------------------
__device__ __forceinline__ void split2(float a, float b, uint32_t& hi, uint32_t& lo) {
    __nv_bfloat16 ha = __float2bfloat16(a);
    __nv_bfloat16 hb = __float2bfloat16(b);
    __nv_bfloat16 la = __float2bfloat16(a - __bfloat162float(ha));
    __nv_bfloat16 lb = __float2bfloat16(b - __bfloat162float(hb));
    hi = ((uint32_t)__bfloat16_as_ushort(hb) << 16) | (uint32_t)__bfloat16_as_ushort(ha);
    lo = ((uint32_t)__bfloat16_as_ushort(lb) << 16) | (uint32_t)__bfloat16_as_ushort(la);
}

__device__ __forceinline__ void mma_bf16(float d[4], const uint32_t a[4],
                                         uint32_t b0, uint32_t b1) {
    asm volatile(
        "mma.sync.aligned.m16n8k16.row.col.f32.bf16.bf16.f32 "
        "{%0,%1,%2,%3}, {%4,%5,%6,%7}, {%8,%9}, {%0,%1,%2,%3};"
        : "+f"(d[0]), "+f"(d[1]), "+f"(d[2]), "+f"(d[3])
        : "r"(a[0]), "r"(a[1]), "r"(a[2]), "r"(a[3]), "r"(b0), "r"(b1));
}

__device__ __forceinline__ uint32_t smem_u32(const void* p) {
    uint32_t a;
    asm("{ .reg .u64 t; cvta.to.shared.u64 t, %1; cvt.u32.u64 %0, t; }" : "=r"(a) : "l"(p));
    return a;
}

#define CP16(dst, src) \
    asm volatile("cp.async.cg.shared.global [%0], [%1], 16;" :: "r"(dst), "l"(src))
#define CPCOMMIT() asm volatile("cp.async.commit_group;" ::: "memory")
#define CPWAIT1()  asm volatile("cp.async.wait_group 1;"  ::: "memory")

#define LDM4(r, a) \
    asm volatile("ldmatrix.sync.aligned.m8n8.x4.shared.b16 {%0,%1,%2,%3}, [%4];" \
        : "=r"((r)[0]), "=r"((r)[1]), "=r"((r)[2]), "=r"((r)[3]) : "r"(a))

__device__ __forceinline__ int poff(int row, int kg) {
    return row * 16 + ((kg ^ ((row >> 1) & 3)) << 2);
}

// ---------------------------------------------------------------------------
// split_tile: x [4096 x 1024] fp32 row-major -> g_x2 chunk blocks (hi/lo).
// grid (C=32, T=32), 256 threads. Coalesced reads AND writes.
// ---------------------------------------------------------------------------
__global__ __launch_bounds__(256) void split_tile(const float* __restrict__ src)
{
    __shared__ float s[128][33];
    const int C = blockIdx.x, T = blockIdx.y;
    const int tid = threadIdx.x;

#pragma unroll
    for (int it = 0; it < 4; it++) {
        const int v  = it * 256 + tid;
        const int r  = v >> 3;
        const int c4 = (v & 7) * 4;
        float4 x4 = *(const float4*)(src + (size_t)(T * 128 + r) * 1024 + C * 32 + c4);
        s[r][c4 + 0] = x4.x; s[r][c4 + 1] = x4.y;
        s[r][c4 + 2] = x4.z; s[r][c4 + 3] = x4.w;
    }
    __syncthreads();

    uint32_t* base = g_x2 + (size_t)(T * 32 + C) * BLK;
#pragma unroll
    for (int it = 0; it < 2; it++) {
        const int task = it * 256 + tid;
        const int row = task >> 2, kg = task & 3;
        uint4 hi, lo;
        split2(s[row][kg * 8 + 0], s[row][kg * 8 + 1], hi.x, lo.x);
        split2(s[row][kg * 8 + 2], s[row][kg * 8 + 3], hi.y, lo.y);
        split2(s[row][kg * 8 + 4], s[row][kg * 8 + 5], hi.z, lo.z);
        split2(s[row][kg * 8 + 6], s[row][kg * 8 + 7], hi.w, lo.w);
        const int po = poff(row, kg);
        *(uint4*)(base + po)       = hi;
        *(uint4*)(base + SUB + po) = lo;
    }
}

// W^T blocks: z = sel*8 + h; rows = e (0..127), k = d. grid (32, 4, 24), (32,8).
__global__ void transpose_w_kernel(const float* __restrict__ Wq,
                                   const float* __restrict__ Wk,
                                   const float* __restrict__ Wv) {
    const int z = blockIdx.z;
    const float* W = ((z < 8) ? Wq : (z < 16) ? Wk : Wv) + (size_t)(z & 7) * D_ * E_;
    __shared__ float tt[32][33];
    const int d0 = blockIdx.x * 32, e0 = blockIdx.y * 32;
    const int tx = threadIdx.x, ty = threadIdx.y;
#pragma unroll
    for (int i = 0; i < 32; i += 8)
        tt[ty + i][tx] = W[(size_t)(d0 + ty + i) * E_ + e0 + tx];   // tt[d_local][e_local]
    __syncthreads();
    if (ty < 4) {
        const int kg = ty;
        const int e  = e0 + tx;          // row 0..127
        uint4 hi, lo;
        split2(tt[kg * 8 + 0][tx], tt[kg * 8 + 1][tx], hi.x, lo.x);
        split2(tt[kg * 8 + 2][tx], tt[kg * 8 + 3][tx], hi.y, lo.y);
        split2(tt[kg * 8 + 4][tx], tt[kg * 8 + 5][tx], hi.z, lo.z);
        split2(tt[kg * 8 + 6][tx], tt[kg * 8 + 7][tx], hi.w, lo.w);
        uint32_t* base = g_w2 + (size_t)(z * 32 + (d0 >> 5)) * BLK;
        const int po = poff(e, kg);
        *(uint4*)(base + po)       = hi;
        *(uint4*)(base + SUB + po) = lo;
    }
}

// Wo^T blocks: rows = n (0..1023 -> nt,nloc), k = h*E+e. grid (32, 32), (32,8).
__global__ void transpose_wo_kernel(const float* __restrict__ Wo) {
    __shared__ float tt[32][33];
    const int k0 = blockIdx.x * 32, n0 = blockIdx.y * 32;
    const int tx = threadIdx.x, ty = threadIdx.y;
#pragma unroll
    for (int i = 0; i < 32; i += 8)
        tt[ty + i][tx] = Wo[(size_t)(k0 + ty + i) * D_ + n0 + tx];  // tt[k_local][n_local]
    __syncthreads();
    if (ty < 4) {
        const int kg   = ty;
        const int nt   = n0 >> 7;
        const int nloc = (n0 & 96) + tx;
        uint4 hi, lo;
        split2(tt[kg * 8 + 0][tx], tt[kg * 8 + 1][tx], hi.x, lo.x);
        split2(tt[kg * 8 + 2][tx], tt[kg * 8 + 3][tx], hi.y, lo.y);
        split2(tt[kg * 8 + 4][tx], tt[kg * 8 + 5][tx], hi.z, lo.z);
        split2(tt[kg * 8 + 6][tx], tt[kg * 8 + 7][tx], hi.w, lo.w);
        uint32_t* base = g_wo2 + (size_t)(nt * 32 + (k0 >> 5)) * BLK;
        const int po = poff(nloc, kg);
        *(uint4*)(base + po)       = hi;
        *(uint4*)(base + SUB + po) = lo;
    }
}

// ---------------------------------------------------------------------------
// bf16x3 mma.sync GEMM: ldmatrix fragments + cp.async 3-stage pipeline.
// Inner body restructured for register headroom: B fragments (8 LDM4) loaded
// once per kk; A fragments loaded per-mt (2 LDM4 live at a time) so ptxas can
// software-pipeline mt+1's loads under mt's 12 mmas.
// Per-accumulator order stays hh->hl->lh (bit-identical results).
// mode 0: Q/K/V (grid 32 x 8 x 3); mode 1: out-proj (grid 32 x 8)
// ---------------------------------------------------------------------------
__global__ __launch_bounds__(256, 2) void gemm128_bf16(
    int mode,
    const float* __restrict__ bq, const float* __restrict__ bk,
    const float* __restrict__ bv, const float* __restrict__ bo,
    float* __restrict__ oout)
{
    extern __shared__ uint32_t dyn[];
    const uint32_t sb = smem_u32(dyn);

    const int tid  = threadIdx.x;
    const int wid  = tid >> 5;
    const int lane = tid & 31;
    const int g    = lane >> 2;      // epilogue row group
    const int t    = lane & 3;       // epilogue col pair
    const int m0   = blockIdx.x * 128;
    const int mb   = (wid & 1) * 64;     // warp m-offset
    const int nb   = (wid >> 1) * 32;    // warp n-offset

    const uint32_t *Asrc, *Bsrc;
    const float* bias;
    if (mode == 0) {
        const int h = blockIdx.y, sel = blockIdx.z;
        Asrc = g_x2 + (size_t)blockIdx.x * 32 * BLK;
        Bsrc = g_w2 + (size_t)(sel * H_ + h) * 32 * BLK;
        bias = ((sel == 0) ? bq : (sel == 1) ? bk : bv) + h * E_;
    } else {
        Asrc = g_a2  + (size_t)blockIdx.x * 32 * BLK;
        Bsrc = g_wo2 + (size_t)blockIdx.y * 32 * BLK;
        bias = bo + blockIdx.y * 128;
    }

    float acc[4][4][4];
#pragma unroll
    for (int i = 0; i < 4; i++)
#pragma unroll
        for (int j = 0; j < 4; j++)
#pragma unroll
            for (int r = 0; r < 4; r++) acc[i][j][r] = 0.f;

    // ldmatrix per-lane bases (standard m16n8k16 fragment <-> x4 matrices)
    const int arow  = mb + (lane & 7) + ((lane >> 3) & 1) * 8;   // + mt*16
    const int akbit = lane >> 4;                                  // k-half
    const int brow  = nb + (lane & 7) + ((lane >> 4) & 1) * 8;   // + p*16
    const int bkbit = (lane >> 3) & 1;

    // identity cp.async: chunk block c -> stage st (A 16 KB then B 16 KB)
    auto issue = [&](int c, int st) {
        const uint32_t dA = sb + st * STG_BYTES;
        const char* sA = (const char*)(Asrc + (size_t)c * BLK);
        const char* sB = (const char*)(Bsrc + (size_t)c * BLK);
#pragma unroll
        for (int j = 0; j < 4; j++) {
            const int v = j * 256 + tid;
            CP16(dA + v * 16,         sA + v * 16);
            CP16(dA + 16384 + v * 16, sB + v * 16);
        }
    };

    issue(0, 0); CPCOMMIT();
    issue(1, 1); CPCOMMIT();

    for (int i = 0; i < 32; i++) {
        CPWAIT1();            // chunk i resident
        __syncthreads();      // publish; prior stage reads complete
        if (i + 2 < 32) issue(i + 2, (i + 2) % 3);
        CPCOMMIT();           // always commit to keep group accounting

        const uint32_t stg = sb + (i % 3) * STG_BYTES;

#pragma unroll
        for (int kk = 0; kk < 2; kk++) {
            // B fragments once per kk (8 LDM4, 32 regs live)
            uint32_t bh[2][4], bl[2][4];
#pragma unroll
            for (int p = 0; p < 2; p++) {
                const int row = brow + p * 16;
                const uint32_t off = row * 64 + (((2 * kk + bkbit) ^ ((row >> 1) & 3)) << 4);
                LDM4(bh[p], stg + 16384 + off);
                LDM4(bl[p], stg + 24576 + off);
            }
            // A fragments per-mt: only 8 regs live -> ptxas can hoist mt+1
#pragma unroll
            for (int mt = 0; mt < 4; mt++) {
                const int row = arow + mt * 16;
                const uint32_t off = row * 64 + (((2 * kk + akbit) ^ ((row >> 1) & 3)) << 4);
                uint32_t ah[4], al[4];
                LDM4(ah, stg + off);
                LDM4(al, stg + 8192 + off);
#pragma unroll
                for (int nt = 0; nt < 4; nt++)
                    mma_bf16(acc[mt][nt], ah,
                             bh[nt >> 1][(nt & 1) * 2], bh[nt >> 1][(nt & 1) * 2 + 1]);
#pragma unroll
                for (int nt = 0; nt < 4; nt++)
                    mma_bf16(acc[mt][nt], ah,
                             bl[nt >> 1][(nt & 1) * 2], bl[nt >> 1][(nt & 1) * 2 + 1]);
#pragma unroll
                for (int nt = 0; nt < 4; nt++)
                    mma_bf16(acc[mt][nt], al,
                             bh[nt >> 1][(nt & 1) * 2], bh[nt >> 1][(nt & 1) * 2 + 1]);
            }
        }
    }

    // epilogue: row = mb+mt*16+g (+8), col = nb+nt*8+2t (+1)
    const int h = blockIdx.y, sel = blockIdx.z;
#pragma unroll
    for (int mt = 0; mt < 4; mt++) {
        const int m_lo = m0 + mb + mt * 16 + g;
#pragma unroll
        for (int rh = 0; rh < 2; rh++) {
            const int m = m_lo + rh * 8;
            float* dst;
            if (mode == 0) {
                const int bb = m >> 11;
                const int s  = m & (S_ - 1);
                float* out = (sel == 0) ? g_q : (sel == 1) ? g_k : g_v;
                dst = out + (((size_t)bb * H_ + h) * S_ + s) * E_;
            } else {
                dst = oout + (size_t)m * D_ + blockIdx.y * 128;
            }
#pragma unroll
            for (int nt = 0; nt < 4; nt++) {
                const int cn = nb + nt * 8 + 2 * t;
                float2 v;
                v.x = acc[mt][nt][2 * rh + 0] + bias[cn];
                v.y = acc[mt][nt][2 * rh + 1] + bias[cn + 1];
                *(float2*)(dst + cn) = v;
            }
        }
    }
}

// ---------------------------------------------------------------------------
// Windowed attention: 8 lanes per query, 4 queries per warp, two-phase.
// Output packed DIRECTLY into g_a2 chunk blocks.
// ---------------------------------------------------------------------------
__global__ __launch_bounds__(256) void attn_kernel(
    const float* __restrict__ bk,
    const float* __restrict__ bv,
    const int*   __restrict__ dilations)
{
    const int gw   = (blockIdx.x * blockDim.x + threadIdx.x) >> 5;  // 0..8191
    const int lane = threadIdx.x & 31;
    const int qi   = lane >> 3;      // query within warp
    const int sl   = lane & 7;       // sub-lane within query
    const int gq   = gw * 4 + qi;    // global query id
    const int s = gq & (S_ - 1);
    const int h = (gq >> 11) & (H_ - 1);
    const int b = gq >> 14;

    const int d = dilations[h];
    const int center = (d * (KW_ - 1)) >> 1;
    const size_t head_base = ((size_t)b * H_ + h) * S_ * E_;
    const int eo = sl * 4;           // float offset within each 32-float band

    float4 q[4], bkr[4];
#pragma unroll
    for (int i = 0; i < 4; i++) {
        q[i]   = *(const float4*)(g_q + head_base + (size_t)s * E_ + i * 32 + eo);
        bkr[i] = *(const float4*)(bk + h * E_ + i * 32 + eo);
    }

    // phase 1: logits
    float logits[KW_];
#pragma unroll
    for (int j = 0; j < KW_; j++) {
        const int pos = s + d * j - center;
        const bool ok = (pos >= 0) && (pos < S_);
        const float* kr = g_k + head_base + (size_t)(ok ? pos : 0) * E_;
        float p = 0.f;
#pragma unroll
        for (int i = 0; i < 4; i++) {
            float4 k4 = ok ? *(const float4*)(kr + i * 32 + eo) : bkr[i];
            p += k4.x * q[i].x + k4.y * q[i].y + k4.z * q[i].z + k4.w * q[i].w;
        }
        p += __shfl_xor_sync(0xffffffffu, p, 1, 8);
        p += __shfl_xor_sync(0xffffffffu, p, 2, 8);
        p += __shfl_xor_sync(0xffffffffu, p, 4, 8);
        logits[j] = p;
    }

    // softmax over KW (identical across the 8 lanes of a query)
    float mx = logits[0];
#pragma unroll
    for (int j = 1; j < KW_; j++) mx = fmaxf(mx, logits[j]);
    float ssum = 0.f;
#pragma unroll
    for (int j = 0; j < KW_; j++) {
        logits[j] = __expf(logits[j] - mx);
        ssum += logits[j];
    }
    const float inv = 0.08838834764831845f / ssum;  // (1/sum) * (1/sqrt(E))

    // phase 2: weighted V accumulation
    float4 acc[4];
#pragma unroll
    for (int i = 0; i < 4; i++) acc[i] = make_float4(0.f, 0.f, 0.f, 0.f);
    float4 bvr[4];
#pragma unroll
    for (int i = 0; i < 4; i++)
        bvr[i] = *(const float4*)(bv + h * E_ + i * 32 + eo);

#pragma unroll
    for (int j = 0; j < KW_; j++) {
        const int pos = s + d * j - center;
        const bool ok = (pos >= 0) && (pos < S_);
        const float* vr = g_v + head_base + (size_t)(ok ? pos : 0) * E_;
        const float w = logits[j] * inv;
#pragma unroll
        for (int i = 0; i < 4; i++) {
            float4 v4 = ok ? *(const float4*)(vr + i * 32 + eo) : bvr[i];
            acc[i].x += w * v4.x; acc[i].y += w * v4.y;
            acc[i].z += w * v4.z; acc[i].w += w * v4.w;
        }
    }

    // pack directly into g_a2: float4 i covers k = h*128 + i*32 + sl*4 .. +3
    const int m    = b * S_ + s;
    const int T    = m >> 7, mloc = m & 127;
    const int kg   = sl >> 1;
    const int sub2 = (sl & 1) * 2;
    const int po   = poff(mloc, kg) + sub2;
#pragma unroll
    for (int i = 0; i < 4; i++) {
        uint32_t h0, l0, h1, l1;
        split2(acc[i].x, acc[i].y, h0, l0);
        split2(acc[i].z, acc[i].w, h1, l1);
        uint32_t* base = g_a2 + (size_t)(T * 32 + h * 4 + i) * BLK;
        base[po]           = h0;
        base[po + 1]       = h1;
        base[SUB + po]     = l0;
        base[SUB + po + 1] = l1;
    }
}

// ---------------------------------------------------------------------------
// Launch
// ---------------------------------------------------------------------------
extern "C" void kernel_launch(void* const* d_in, const int* in_sizes, int n_in,
                              void* d_out, int out_size)
{
    const float* x  = (const float*)d_in[0];
    const float* Wq = (const float*)d_in[1];
    const float* bq = (const float*)d_in[2];
    const float* Wk = (const float*)d_in[3];
    const float* bk = (const float*)d_in[4];
    const float* Wv = (const float*)d_in[5];
    const float* bv = (const float*)d_in[6];
    const float* Wo = (const float*)d_in[7];
    const float* bo = (const float*)d_in[8];
    const int*   dl = (const int*)d_in[9];
    float* out = (float*)d_out;

    // Not a stream op; graph-capture safe. Unconditional (no static guards).
    cudaFuncSetAttribute(gemm128_bf16, cudaFuncAttributeMaxDynamicSharedMemorySize, GEMM_SMEM);

    // prep: pack operands into chunk blocks
    split_tile<<<dim3(32, 32), 256>>>(x);
    transpose_w_kernel<<<dim3(32, 4, 24), dim3(32, 8)>>>(Wq, Wk, Wv);
    transpose_wo_kernel<<<dim3(32, 32), dim3(32, 8)>>>(Wo);

    // Q/K/V projections on tensor cores (bf16x3, ldmatrix path)
    gemm128_bf16<<<dim3(M_ / 128, H_, 3), 256, GEMM_SMEM>>>(0, bq, bk, bv, bo, out);

    // windowed attention, packs g_a2 directly
    attn_kernel<<<1024, 256>>>(bk, bv, dl);

    // out-projection on tensor cores (bf16x3)
    gemm128_bf16<<<dim3(M_ / 128, D_ / 128, 1), 256, GEMM_SMEM>>>(1, bq, bk, bv, bo, out);
}